// round 9
// baseline (speedup 1.0000x reference)
#include <cuda_runtime.h>
#include <cstdint>
#include <cstddef>

// Problem constants
#define BB 2
#define TT 2048
#define CC 1024
#define HH 16
#define DD 64
#define MTOT (BB*TT)          // 4096 rows

// ---------------------------------------------------------------------------
// Scratch: exactly 64 MiB (proven-passing footprint). Overlays:
//   g_att holds w_qkv^T before flash, attention output after.
//   g_qkv[0:1M] holds w_proj^T after flash.
// ---------------------------------------------------------------------------
__device__ float g_qkv[(size_t)MTOT * 3 * CC];   // 48 MiB
__device__ float g_att[(size_t)MTOT * CC];       // 16 MiB

// ---------------------------------------------------------------------------
// Helpers
// ---------------------------------------------------------------------------
__device__ __forceinline__ float to_tf32(float x) {
    uint32_t y;
    asm("cvt.rna.tf32.f32 %0, %1;" : "=r"(y) : "f"(x));
    return __uint_as_float(y);
}
__device__ __forceinline__ uint32_t cvt_reg(uint32_t r) {
    uint32_t y;
    asm("cvt.rna.tf32.f32 %0, %1;" : "=r"(y) : "f"(__uint_as_float(r)));
    return y;
}

__device__ __forceinline__ void mma8(float d[4], const uint32_t a[4],
                                     uint32_t b0, uint32_t b1) {
    asm volatile(
        "mma.sync.aligned.m16n8k8.row.col.f32.tf32.tf32.f32 "
        "{%0,%1,%2,%3}, {%4,%5,%6,%7}, {%8,%9}, {%0,%1,%2,%3};\n"
        : "+f"(d[0]), "+f"(d[1]), "+f"(d[2]), "+f"(d[3])
        : "r"(a[0]), "r"(a[1]), "r"(a[2]), "r"(a[3]), "r"(b0), "r"(b1));
}

__device__ __forceinline__ void ldsm4(uint32_t& r0, uint32_t& r1,
                                      uint32_t& r2, uint32_t& r3, uint32_t addr) {
    asm volatile("ldmatrix.sync.aligned.m8n8.x4.shared.b16 {%0,%1,%2,%3}, [%4];"
                 : "=r"(r0), "=r"(r1), "=r"(r2), "=r"(r3) : "r"(addr));
}

__device__ __forceinline__ void cp_async16(void* smem_dst, const float* gsrc) {
    uint32_t s = (uint32_t)__cvta_generic_to_shared(smem_dst);
    asm volatile("cp.async.cg.shared.global [%0], [%1], 16;\n"
                 :: "r"(s), "l"(gsrc) : "memory");
}
#define CP_COMMIT() asm volatile("cp.async.commit_group;\n" ::: "memory")
#define CP_WAIT0()  asm volatile("cp.async.wait_group 0;\n" ::: "memory")

__device__ __forceinline__ uint32_t smem_u32(const void* p) {
    return (uint32_t)__cvta_generic_to_shared(p);
}

// ---------------------------------------------------------------------------
// Transpose + tf32-convert: Wt[n][k] = cvt(W[k][n]).  W is [K][N].
// ---------------------------------------------------------------------------
__device__ __forceinline__ void
transpose_cvt_body(const float* __restrict__ W, float* __restrict__ Wt,
                   int K, int N)
{
    __shared__ float tile[32][33];
    int n0 = blockIdx.x * 32, k0 = blockIdx.y * 32;
    int tx = threadIdx.x, ty = threadIdx.y;
#pragma unroll
    for (int i = 0; i < 4; i++)
        tile[ty + 8 * i][tx] = W[(size_t)(k0 + ty + 8 * i) * N + n0 + tx];
    __syncthreads();
#pragma unroll
    for (int i = 0; i < 4; i++)
        Wt[(size_t)(n0 + ty + 8 * i) * K + k0 + tx] = to_tf32(tile[tx][ty + 8 * i]);
}
__global__ void transpose_wqkv_kernel(const float* __restrict__ w_qkv) {
    transpose_cvt_body(w_qkv, g_att, CC, 3 * CC);
}
__global__ void transpose_wproj_kernel(const float* __restrict__ w_proj) {
    transpose_cvt_body(w_proj, g_qkv, CC, CC);
}

// ---------------------------------------------------------------------------
// tf32 GEMM (R6, passing): C = A @ Bt^T (+bias). cp.async 2-stage, ldmatrix.
// Block tile 128x128, BK=32, 256 threads (8 warps = 4m x 2n, 32x64 each).
// ---------------------------------------------------------------------------
#define GP 36
#define GSTG (128*GP)
#define GEMM_SMEM (4*GSTG*4)   // 73728 B

__device__ __forceinline__ void
gemm_stage(const float* __restrict__ src, float* dst, int K, int k0, int tid)
{
#pragma unroll
    for (int t = 0; t < 4; t++) {
        int f = tid + t * 256;
        int row = f >> 3, c4 = f & 7;
        cp_async16(dst + row * GP + c4 * 4, src + (size_t)row * K + k0 + c4 * 4);
    }
}

template<int ACVT, int ROUND, int HASBIAS>
__device__ __forceinline__ void
gemm_body(const float* __restrict__ A, const float* __restrict__ Bt,
          const float* __restrict__ bias, float* __restrict__ C, int N, int K)
{
    extern __shared__ float sm[];
    float* As = sm;
    float* Bs = sm + 2 * GSTG;

    const int tid  = threadIdx.x;
    const int bm   = blockIdx.y;
    const int bn   = blockIdx.x;
    const int warp = tid >> 5;
    const int lane = tid & 31;
    const int wm   = warp & 3;
    const int wn   = warp >> 2;
    const int g    = lane >> 2;
    const int tir  = lane & 3;

    const int aRow = (lane & 7) + ((lane >> 3) & 1) * 8;
    const int aCol = (lane >> 4) * 4;
    const int bRow = (lane & 7) + (lane >> 4) * 8;
    const int bCol = ((lane >> 3) & 1) * 4;

    const uint32_t aBase = smem_u32(As) + (((wm * 32 + aRow) * GP + aCol) << 2);
    const uint32_t bBase = smem_u32(Bs) + (((wn * 64 + bRow) * GP + bCol) << 2);

    float acc[2][8][4];
#pragma unroll
    for (int mt = 0; mt < 2; mt++)
#pragma unroll
        for (int nt = 0; nt < 8; nt++)
#pragma unroll
            for (int i = 0; i < 4; i++) acc[mt][nt][i] = 0.0f;

    const float* Ablk = A  + (size_t)(bm * 128) * K;
    const float* Bblk = Bt + (size_t)(bn * 128) * K;
    const int NT = K >> 5;

    gemm_stage(Ablk, As, K, 0, tid);
    gemm_stage(Bblk, Bs, K, 0, tid);
    CP_COMMIT();

    for (int it = 0; it < NT; it++) {
        CP_WAIT0();
        __syncthreads();
        if (it + 1 < NT) {
            int nb = (it + 1) & 1;
            gemm_stage(Ablk, As + nb * GSTG, K, (it + 1) * 32, tid);
            gemm_stage(Bblk, Bs + nb * GSTG, K, (it + 1) * 32, tid);
            CP_COMMIT();
        }
        const uint32_t stg = (uint32_t)((it & 1) * GSTG * 4);

#pragma unroll
        for (int kk = 0; kk < 4; kk++) {
            const uint32_t kb4 = (uint32_t)(kk * 8 * 4);
            uint32_t a[2][4];
            ldsm4(a[0][0], a[0][1], a[0][2], a[0][3], aBase + stg + kb4);
            ldsm4(a[1][0], a[1][1], a[1][2], a[1][3],
                  aBase + stg + kb4 + (16 * GP << 2));
            if (ACVT) {
#pragma unroll
                for (int mt = 0; mt < 2; mt++)
#pragma unroll
                    for (int i = 0; i < 4; i++) a[mt][i] = cvt_reg(a[mt][i]);
            }
            uint32_t b[4][4];
#pragma unroll
            for (int ng = 0; ng < 4; ng++)
                ldsm4(b[ng][0], b[ng][1], b[ng][2], b[ng][3],
                      bBase + stg + kb4 + (uint32_t)(ng * 16 * GP << 2));
#pragma unroll
            for (int ng = 0; ng < 4; ng++) {
                mma8(acc[0][2*ng  ], a[0], b[ng][0], b[ng][1]);
                mma8(acc[0][2*ng+1], a[0], b[ng][2], b[ng][3]);
                mma8(acc[1][2*ng  ], a[1], b[ng][0], b[ng][1]);
                mma8(acc[1][2*ng+1], a[1], b[ng][2], b[ng][3]);
            }
        }
        __syncthreads();
    }

#pragma unroll
    for (int mt = 0; mt < 2; mt++) {
#pragma unroll
        for (int nt = 0; nt < 8; nt++) {
            int row = bm * 128 + wm * 32 + mt * 16 + g;
            int col = bn * 128 + wn * 64 + nt * 8 + tir * 2;
            float bb0 = 0.f, bb1 = 0.f;
            if (HASBIAS) { bb0 = bias[col]; bb1 = bias[col + 1]; }
            float v00 = acc[mt][nt][0] + bb0, v01 = acc[mt][nt][1] + bb1;
            float v10 = acc[mt][nt][2] + bb0, v11 = acc[mt][nt][3] + bb1;
            if (ROUND) {
                v00 = to_tf32(v00); v01 = to_tf32(v01);
                v10 = to_tf32(v10); v11 = to_tf32(v11);
            }
            *(float2*)(C + (size_t)row * N + col)       = make_float2(v00, v01);
            *(float2*)(C + (size_t)(row + 8) * N + col) = make_float2(v10, v11);
        }
    }
}

__global__ void __launch_bounds__(256, 2)
gemm_qkv_kernel(const float* __restrict__ x)
{
    gemm_body<1, 1, 0>(x, g_att, nullptr, g_qkv, 3 * CC, CC);
}
__global__ void __launch_bounds__(256, 2)
gemm_proj_kernel(const float* __restrict__ b_proj, float* __restrict__ out)
{
    gemm_body<0, 0, 1>(g_att, g_qkv, b_proj, out, CC, CC);
}

// ---------------------------------------------------------------------------
// Flash attention (causal), tf32 mma.
// Changes vs R6: exp2 softmax (log2e folded into Q, re-rounded to tf32);
// V stored as pairs [pr][col][2] -> one LDS.64 per B-fragment (was 2 LDS.32);
// single-buffered K/V -> smem 103936 B -> 2 CTAs/SM for cross-CTA overlap.
// grid = (T/128, B*H). 8 warps; warp w owns q-rows [w*16, w*16+16).
// ---------------------------------------------------------------------------
#define FP 68
#define VP2 132                       // words per V pair-row (2*64 + pad)
#define FLASH_SMEM ((128*FP + 128*FP + 64*FP + 32*VP2)*4)   // 103936 B

__global__ void __launch_bounds__(256)
flash_kernel()
{
    extern __shared__ float fsm[];
    float* Qs = fsm;                       // 128 x FP
    float* Ps = fsm + 128 * FP;            // 128 x FP
    float* Ks = fsm + 2 * 128 * FP;        // 64 x FP
    float* Vs = Ks + 64 * FP;              // 32 x VP2 (pairs)

    const float* qkv = g_qkv;
    float* O = g_att;

    const int qb  = (gridDim.x - 1) - blockIdx.x;   // heavy blocks first
    const int bh  = blockIdx.y;
    const int b   = bh >> 4;
    const int h   = bh & 15;
    const int tid = threadIdx.x;
    const int w   = tid >> 5;
    const int lane = tid & 31;
    const int g   = lane >> 2;
    const int tir = lane & 3;

    const int aRow = (lane & 7) + ((lane >> 3) & 1) * 8;
    const int aCol = (lane >> 4) * 4;
    const int bRow = (lane & 7) + (lane >> 4) * 8;
    const int bCol = ((lane >> 3) & 1) * 4;

    const uint32_t qBase = smem_u32(Qs) + (((w * 16 + aRow) * FP + aCol) << 2);
    const uint32_t pBase = smem_u32(Ps) + (((w * 16 + aRow) * FP + aCol) << 2);
    const uint32_t kBase = smem_u32(Ks) + ((bRow * FP + bCol) << 2);

    // 1/sqrt(64) * log2(e): exp2-domain scores
    const float scale = 0.125f * 1.44269504088896340736f;
    const size_t rowstride = 3 * CC;
    const float* qbase = qkv + (size_t)(b * TT) * rowstride + h * DD;
    const float* kbase = qbase + CC;
    const float* vbase = qbase + 2 * CC;

    const int jmax = 2 * qb + 1;

    // ---- load Q tile (128x64), scaled and re-rounded to tf32 ----
#pragma unroll
    for (int t = 0; t < 8; t++) {
        int f   = tid + t * 256;
        int row = f >> 4;
        int c4  = f & 15;
        float4 v = *(const float4*)(qbase + (size_t)(qb * 128 + row) * rowstride + c4 * 4);
        float* dst = &Qs[row * FP + c4 * 4];
        dst[0] = to_tf32(v.x * scale); dst[1] = to_tf32(v.y * scale);
        dst[2] = to_tf32(v.z * scale); dst[3] = to_tf32(v.w * scale);
    }

    float m0 = -1e30f, m1 = -1e30f;
    float l0 = 0.f, l1 = 0.f;
    float o[8][4];
#pragma unroll
    for (int nt = 0; nt < 8; nt++)
#pragma unroll
        for (int i = 0; i < 4; i++) o[nt][i] = 0.f;

    for (int j = 0; j <= jmax; j++) {
        // ---- stage K (cp.async) and V (LDG + paired STS) ----
#pragma unroll
        for (int t = 0; t < 4; t++) {
            int f = tid + t * 256;
            int ky = f >> 4, c4 = f & 15;
            size_t goff = (size_t)(j * 64 + ky) * rowstride + c4 * 4;
            cp_async16(Ks + ky * FP + c4 * 4, kbase + goff);
            float4 v = *(const float4*)(vbase + goff);
            int pr  = 4 * (ky >> 3) + (ky & 3);
            int sel = (ky >> 2) & 1;
            float* vd = Vs + pr * VP2 + sel;
            vd[8 * c4 + 0] = v.x;
            vd[8 * c4 + 2] = v.y;
            vd[8 * c4 + 4] = v.z;
            vd[8 * c4 + 6] = v.w;
        }
        CP_COMMIT();
        CP_WAIT0();
        __syncthreads();

        // ---- S = Q @ K^T (exp2-domain) : warp computes 16x64 ----
        float s[8][4];
#pragma unroll
        for (int nt = 0; nt < 8; nt++)
#pragma unroll
            for (int i = 0; i < 4; i++) s[nt][i] = 0.f;

#pragma unroll
        for (int kk = 0; kk < 8; kk++) {
            const uint32_t kb4 = (uint32_t)(kk * 8 * 4);
            uint32_t a[4];
            ldsm4(a[0], a[1], a[2], a[3], qBase + kb4);
            uint32_t bk[4][4];
#pragma unroll
            for (int ng = 0; ng < 4; ng++)
                ldsm4(bk[ng][0], bk[ng][1], bk[ng][2], bk[ng][3],
                      kBase + kb4 + (uint32_t)(ng * 16 * FP << 2));
#pragma unroll
            for (int ng = 0; ng < 4; ng++) {
                mma8(s[2*ng  ], a, bk[ng][0], bk[ng][1]);
                mma8(s[2*ng+1], a, bk[ng][2], bk[ng][3]);
            }
        }

        // ---- causal mask (diagonal-region blocks only) ----
        if (j >= 2 * qb) {
            const int qr0 = qb * 128 + w * 16 + g;
            const int qr1 = qr0 + 8;
            const int jc  = j * 64;
#pragma unroll
            for (int nt = 0; nt < 8; nt++) {
                int c0 = jc + nt * 8 + tir * 2;
                int c1 = c0 + 1;
                if (c0 > qr0) s[nt][0] = -1e30f;
                if (c1 > qr0) s[nt][1] = -1e30f;
                if (c0 > qr1) s[nt][2] = -1e30f;
                if (c1 > qr1) s[nt][3] = -1e30f;
            }
        }

        // ---- online softmax (exp2 domain) ----
        float rm0 = -1e30f, rm1 = -1e30f;
#pragma unroll
        for (int nt = 0; nt < 8; nt++) {
            rm0 = fmaxf(rm0, fmaxf(s[nt][0], s[nt][1]));
            rm1 = fmaxf(rm1, fmaxf(s[nt][2], s[nt][3]));
        }
        rm0 = fmaxf(rm0, __shfl_xor_sync(0xffffffffu, rm0, 1));
        rm0 = fmaxf(rm0, __shfl_xor_sync(0xffffffffu, rm0, 2));
        rm1 = fmaxf(rm1, __shfl_xor_sync(0xffffffffu, rm1, 1));
        rm1 = fmaxf(rm1, __shfl_xor_sync(0xffffffffu, rm1, 2));

        float nm0 = fmaxf(m0, rm0), nm1 = fmaxf(m1, rm1);
        float cf0 = exp2f(m0 - nm0), cf1 = exp2f(m1 - nm1);
        m0 = nm0; m1 = nm1;

        float rs0 = 0.f, rs1 = 0.f;
        const int prow = w * 16 + g;
#pragma unroll
        for (int nt = 0; nt < 8; nt++) {
            int c = nt * 8 + tir * 2;
            float p0 = exp2f(s[nt][0] - nm0);
            float p1 = exp2f(s[nt][1] - nm0);
            float p2 = exp2f(s[nt][2] - nm1);
            float p3 = exp2f(s[nt][3] - nm1);
            rs0 += p0 + p1;
            rs1 += p2 + p3;
            *(float2*)&Ps[(prow    ) * FP + c] =
                make_float2(to_tf32(p0), to_tf32(p1));
            *(float2*)&Ps[(prow + 8) * FP + c] =
                make_float2(to_tf32(p2), to_tf32(p3));
        }
        rs0 += __shfl_xor_sync(0xffffffffu, rs0, 1);
        rs0 += __shfl_xor_sync(0xffffffffu, rs0, 2);
        rs1 += __shfl_xor_sync(0xffffffffu, rs1, 1);
        rs1 += __shfl_xor_sync(0xffffffffu, rs1, 2);
        l0 = l0 * cf0 + rs0;
        l1 = l1 * cf1 + rs1;

#pragma unroll
        for (int nt = 0; nt < 8; nt++) {
            o[nt][0] *= cf0; o[nt][1] *= cf0;
            o[nt][2] *= cf1; o[nt][3] *= cf1;
        }

        __syncwarp();   // Ps rows are per-warp private

        // ---- O += P @ V  (paired LDS.64 fragments) ----
#pragma unroll
        for (int kk = 0; kk < 8; kk++) {
            const int kb = kk * 8;
            uint32_t a[4];
            ldsm4(a[0], a[1], a[2], a[3], pBase + (uint32_t)(kb << 2));
            const float* vrow = Vs + (4 * kk + tir) * VP2 + 2 * g;
#pragma unroll
            for (int nt = 0; nt < 8; nt++) {
                float2 bv = *(const float2*)(vrow + nt * 16);
                mma8(o[nt], a, __float_as_uint(bv.x), __float_as_uint(bv.y));
            }
        }
        __syncthreads();   // all reads done before next stage overwrites
    }

    // ---- normalize, round to tf32 (proj GEMM A operand), write [B,T,C] ----
    const float inv0 = 1.f / l0;
    const float inv1 = 1.f / l1;
    const int t0 = qb * 128 + w * 16 + g;
#pragma unroll
    for (int nt = 0; nt < 8; nt++) {
        int d = nt * 8 + tir * 2;
        float2 v0 = make_float2(to_tf32(o[nt][0] * inv0), to_tf32(o[nt][1] * inv0));
        float2 v1 = make_float2(to_tf32(o[nt][2] * inv1), to_tf32(o[nt][3] * inv1));
        *(float2*)(O + (size_t)(b * TT + t0    ) * CC + h * DD + d) = v0;
        *(float2*)(O + (size_t)(b * TT + t0 + 8) * CC + h * DD + d) = v1;
    }
}

// ---------------------------------------------------------------------------
// Launch
// ---------------------------------------------------------------------------
extern "C" void kernel_launch(void* const* d_in, const int* in_sizes, int n_in,
                              void* d_out, int out_size)
{
    const float* x      = (const float*)d_in[0];
    const float* w_qkv  = (const float*)d_in[1];
    const float* w_proj = (const float*)d_in[2];
    const float* b_proj = (const float*)d_in[3];
    float* out = (float*)d_out;

    cudaFuncSetAttribute(gemm_qkv_kernel,
                         cudaFuncAttributeMaxDynamicSharedMemorySize, GEMM_SMEM);
    cudaFuncSetAttribute(gemm_proj_kernel,
                         cudaFuncAttributeMaxDynamicSharedMemorySize, GEMM_SMEM);
    cudaFuncSetAttribute(flash_kernel,
                         cudaFuncAttributeMaxDynamicSharedMemorySize, FLASH_SMEM);

    // 0) w_qkv -> w_qkv^T in g_att
    transpose_wqkv_kernel<<<dim3(3 * CC / 32, CC / 32), dim3(32, 8)>>>(w_qkv);

    // 1) QKV projection: x @ w_qkv -> g_qkv (tf32-rounded)
    gemm_qkv_kernel<<<dim3(3 * CC / 128, MTOT / 128), 256, GEMM_SMEM>>>(x);

    // 2) Fused causal flash attention: g_qkv -> g_att
    flash_kernel<<<dim3(TT / 128, BB * HH), 256, FLASH_SMEM>>>();

    // 3) w_proj -> w_proj^T into g_qkv[0:1M]
    transpose_wproj_kernel<<<dim3(CC / 32, CC / 32), dim3(32, 8)>>>(w_proj);

    // 4) Output projection + bias: g_att @ w_proj -> out
    gemm_proj_kernel<<<dim3(CC / 128, MTOT / 128), 256, GEMM_SMEM>>>(b_proj, out);
}

// round 11
// speedup vs baseline: 1.1887x; 1.1887x over previous
#include <cuda_runtime.h>
#include <cstdint>
#include <cstddef>

// Problem constants
#define BB 2
#define TT 2048
#define CC 1024
#define HH 16
#define DD 64
#define MTOT (BB*TT)          // 4096 rows

// ---------------------------------------------------------------------------
// Scratch: exactly 64 MiB. g_qkv layout (floats):
//   [0 : 8M)   QK region: [4096][2048] rows of Q|K (tf32-rounded)
//   [8M : 12M) Vt region: [B*H*D][T] = [2048][2048], V transposed (tf32)
// Overlays: g_att = w_qkv^T before flash, attention output after;
//           g_qkv[0:1M] = w_proj^T after flash (QK region dead then).
// ---------------------------------------------------------------------------
#define QKS 2048                         // QK region row stride (floats)
#define VT_OFF ((size_t)MTOT * 2 * CC)   // 8M floats
__device__ float g_qkv[(size_t)MTOT * 3 * CC];   // 48 MiB
__device__ float g_att[(size_t)MTOT * CC];       // 16 MiB

// ---------------------------------------------------------------------------
// Helpers
// ---------------------------------------------------------------------------
__device__ __forceinline__ float to_tf32(float x) {
    uint32_t y;
    asm("cvt.rna.tf32.f32 %0, %1;" : "=r"(y) : "f"(x));
    return __uint_as_float(y);
}
__device__ __forceinline__ uint32_t cvt_reg(uint32_t r) {
    uint32_t y;
    asm("cvt.rna.tf32.f32 %0, %1;" : "=r"(y) : "f"(__uint_as_float(r)));
    return y;
}

__device__ __forceinline__ void mma8(float d[4], const uint32_t a[4],
                                     uint32_t b0, uint32_t b1) {
    asm volatile(
        "mma.sync.aligned.m16n8k8.row.col.f32.tf32.tf32.f32 "
        "{%0,%1,%2,%3}, {%4,%5,%6,%7}, {%8,%9}, {%0,%1,%2,%3};\n"
        : "+f"(d[0]), "+f"(d[1]), "+f"(d[2]), "+f"(d[3])
        : "r"(a[0]), "r"(a[1]), "r"(a[2]), "r"(a[3]), "r"(b0), "r"(b1));
}

__device__ __forceinline__ void ldsm4(uint32_t& r0, uint32_t& r1,
                                      uint32_t& r2, uint32_t& r3, uint32_t addr) {
    asm volatile("ldmatrix.sync.aligned.m8n8.x4.shared.b16 {%0,%1,%2,%3}, [%4];"
                 : "=r"(r0), "=r"(r1), "=r"(r2), "=r"(r3) : "r"(addr));
}

__device__ __forceinline__ void cp_async16(void* smem_dst, const void* gsrc) {
    uint32_t s = (uint32_t)__cvta_generic_to_shared(smem_dst);
    asm volatile("cp.async.cg.shared.global [%0], [%1], 16;\n"
                 :: "r"(s), "l"(gsrc) : "memory");
}
#define CP_COMMIT() asm volatile("cp.async.commit_group;\n" ::: "memory")
#define CP_WAIT0()  asm volatile("cp.async.wait_group 0;\n" ::: "memory")

__device__ __forceinline__ uint32_t smem_u32(const void* p) {
    return (uint32_t)__cvta_generic_to_shared(p);
}

// ---------------------------------------------------------------------------
// Transpose + tf32-convert: Wt[n][k] = cvt(W[k][n]).  W is [K][N].
// ---------------------------------------------------------------------------
__device__ __forceinline__ void
transpose_cvt_body(const float* __restrict__ W, float* __restrict__ Wt,
                   int K, int N)
{
    __shared__ float tile[32][33];
    int n0 = blockIdx.x * 32, k0 = blockIdx.y * 32;
    int tx = threadIdx.x, ty = threadIdx.y;
#pragma unroll
    for (int i = 0; i < 4; i++)
        tile[ty + 8 * i][tx] = W[(size_t)(k0 + ty + 8 * i) * N + n0 + tx];
    __syncthreads();
#pragma unroll
    for (int i = 0; i < 4; i++)
        Wt[(size_t)(n0 + ty + 8 * i) * K + k0 + tx] = to_tf32(tile[tx][ty + 8 * i]);
}
__global__ void transpose_wqkv_kernel(const float* __restrict__ w_qkv) {
    transpose_cvt_body(w_qkv, g_att, CC, 3 * CC);
}
__global__ void transpose_wproj_kernel(const float* __restrict__ w_proj) {
    transpose_cvt_body(w_proj, g_qkv, CC, CC);
}

// ---------------------------------------------------------------------------
// tf32 GEMM (R6 core, passing): C = A @ Bt^T (+bias). cp.async 2-stage,
// ldmatrix fragments. 128x128 tile, BK=32, 256 threads.
// QKVOUT: split epilogue — cols<2048 to QK region [row][2048]; cols>=2048
// transposed into Vt region [b*1024 + (col-2048)][t]. All tf32-rounded.
// ---------------------------------------------------------------------------
#define GP 36
#define GSTG (128*GP)
#define GEMM_SMEM (4*GSTG*4)   // 73728 B

__device__ __forceinline__ void
gemm_stage(const float* __restrict__ src, float* dst, int K, int k0, int tid)
{
#pragma unroll
    for (int t = 0; t < 4; t++) {
        int f = tid + t * 256;
        int row = f >> 3, c4 = f & 7;
        cp_async16(dst + row * GP + c4 * 4, src + (size_t)row * K + k0 + c4 * 4);
    }
}

template<int ACVT, int ROUND, int HASBIAS, int QKVOUT>
__device__ __forceinline__ void
gemm_body(const float* __restrict__ A, const float* __restrict__ Bt,
          const float* __restrict__ bias, float* __restrict__ C, int N, int K)
{
    extern __shared__ float sm[];
    float* As = sm;
    float* Bs = sm + 2 * GSTG;

    const int tid  = threadIdx.x;
    const int bm   = blockIdx.y;
    const int bn   = blockIdx.x;
    const int warp = tid >> 5;
    const int lane = tid & 31;
    const int wm   = warp & 3;
    const int wn   = warp >> 2;
    const int g    = lane >> 2;
    const int tir  = lane & 3;

    const int aRow = (lane & 7) + ((lane >> 3) & 1) * 8;
    const int aCol = (lane >> 4) * 4;
    const int bRow = (lane & 7) + (lane >> 4) * 8;
    const int bCol = ((lane >> 3) & 1) * 4;

    const uint32_t aBase = smem_u32(As) + (((wm * 32 + aRow) * GP + aCol) << 2);
    const uint32_t bBase = smem_u32(Bs) + (((wn * 64 + bRow) * GP + bCol) << 2);

    float acc[2][8][4];
#pragma unroll
    for (int mt = 0; mt < 2; mt++)
#pragma unroll
        for (int nt = 0; nt < 8; nt++)
#pragma unroll
            for (int i = 0; i < 4; i++) acc[mt][nt][i] = 0.0f;

    const float* Ablk = A  + (size_t)(bm * 128) * K;
    const float* Bblk = Bt + (size_t)(bn * 128) * K;
    const int NT = K >> 5;

    gemm_stage(Ablk, As, K, 0, tid);
    gemm_stage(Bblk, Bs, K, 0, tid);
    CP_COMMIT();

    for (int it = 0; it < NT; it++) {
        CP_WAIT0();
        __syncthreads();
        if (it + 1 < NT) {
            int nb = (it + 1) & 1;
            gemm_stage(Ablk, As + nb * GSTG, K, (it + 1) * 32, tid);
            gemm_stage(Bblk, Bs + nb * GSTG, K, (it + 1) * 32, tid);
            CP_COMMIT();
        }
        const uint32_t stg = (uint32_t)((it & 1) * GSTG * 4);

#pragma unroll
        for (int kk = 0; kk < 4; kk++) {
            const uint32_t kb4 = (uint32_t)(kk * 8 * 4);
            uint32_t a[2][4];
            ldsm4(a[0][0], a[0][1], a[0][2], a[0][3], aBase + stg + kb4);
            ldsm4(a[1][0], a[1][1], a[1][2], a[1][3],
                  aBase + stg + kb4 + (16 * GP << 2));
            if (ACVT) {
#pragma unroll
                for (int mt = 0; mt < 2; mt++)
#pragma unroll
                    for (int i = 0; i < 4; i++) a[mt][i] = cvt_reg(a[mt][i]);
            }
            uint32_t b[4][4];
#pragma unroll
            for (int ng = 0; ng < 4; ng++)
                ldsm4(b[ng][0], b[ng][1], b[ng][2], b[ng][3],
                      bBase + stg + kb4 + (uint32_t)(ng * 16 * GP << 2));
#pragma unroll
            for (int ng = 0; ng < 4; ng++) {
                mma8(acc[0][2*ng  ], a[0], b[ng][0], b[ng][1]);
                mma8(acc[0][2*ng+1], a[0], b[ng][2], b[ng][3]);
                mma8(acc[1][2*ng  ], a[1], b[ng][0], b[ng][1]);
                mma8(acc[1][2*ng+1], a[1], b[ng][2], b[ng][3]);
            }
        }
        __syncthreads();
    }

#pragma unroll
    for (int mt = 0; mt < 2; mt++) {
#pragma unroll
        for (int nt = 0; nt < 8; nt++) {
            int row = bm * 128 + wm * 32 + mt * 16 + g;
            int col = bn * 128 + wn * 64 + nt * 8 + tir * 2;
            float bb0 = 0.f, bb1 = 0.f;
            if (HASBIAS) { bb0 = bias[col]; bb1 = bias[col + 1]; }
            float v00 = acc[mt][nt][0] + bb0, v01 = acc[mt][nt][1] + bb1;
            float v10 = acc[mt][nt][2] + bb0, v11 = acc[mt][nt][3] + bb1;
            if (ROUND) {
                v00 = to_tf32(v00); v01 = to_tf32(v01);
                v10 = to_tf32(v10); v11 = to_tf32(v11);
            }
            if (QKVOUT) {
                if (col < 2 * CC) {
                    // QK region: [row][2048]
                    *(float2*)(C + (size_t)row * QKS + col)       = make_float2(v00, v01);
                    *(float2*)(C + (size_t)(row + 8) * QKS + col) = make_float2(v10, v11);
                } else {
                    // Vt region: [b*1024 + hd][t]  (transpose scatter)
                    int b  = row >> 11;
                    int t  = row & 2047;
                    int hd = col - 2 * CC;
                    float* vt = C + VT_OFF + (size_t)(b * 1024 + hd) * TT + t;
                    vt[0]            = v00;   // (hd,   t)
                    vt[8]            = v10;   // (hd,   t+8)
                    vt[TT]           = v01;   // (hd+1, t)
                    vt[TT + 8]       = v11;   // (hd+1, t+8)
                }
            } else {
                *(float2*)(C + (size_t)row * N + col)       = make_float2(v00, v01);
                *(float2*)(C + (size_t)(row + 8) * N + col) = make_float2(v10, v11);
            }
        }
    }
}

__global__ void __launch_bounds__(256, 2)
gemm_qkv_kernel(const float* __restrict__ x)
{
    gemm_body<1, 1, 0, 1>(x, g_att, nullptr, g_qkv, 3 * CC, CC);
}
__global__ void __launch_bounds__(256, 2)
gemm_proj_kernel(const float* __restrict__ b_proj, float* __restrict__ out)
{
    gemm_body<0, 0, 1, 0>(g_att, g_qkv, b_proj, out, CC, CC);
}

// ---------------------------------------------------------------------------
// Flash attention (causal), all-tf32, exp2-domain softmax.
// R6 double-buffered cp.async skeleton. New:
//  - V staged from the TRANSPOSED global Vt region -> PV B-fragments via
//    ldmatrix (same addressing as K): no scalar V loads.
//  - Q fragments hoisted to registers (loop-invariant); Ps overlays Qs.
// smem = 104448 B -> 2 CTAs/SM. grid = (T/128, B*H), 8 warps.
// ---------------------------------------------------------------------------
#define FP 68
#define QP_OFF 0                          // Qs then Ps (overlay): 128 x FP
#define KS_OFF (128*FP*4)                 // 34816
#define KSTG_B (64*FP*4)                  // 17408
#define VS_OFF (KS_OFF + 2*KSTG_B)        // 69632
#define FLASH_SMEM (VS_OFF + 2*KSTG_B)    // 104448

__global__ void __launch_bounds__(256, 2)
flash_kernel()
{
    extern __shared__ char fsm[];
    float* Qs = (float*)(fsm + QP_OFF);   // doubles as Ps after frag hoist

    const float* qkv = g_qkv;
    float* O = g_att;

    const int qb  = (gridDim.x - 1) - blockIdx.x;   // heavy blocks first
    const int bh  = blockIdx.y;
    const int b   = bh >> 4;
    const int h   = bh & 15;
    const int tid = threadIdx.x;
    const int w   = tid >> 5;
    const int lane = tid & 31;
    const int g   = lane >> 2;
    const int tir = lane & 3;

    const int aRow = (lane & 7) + ((lane >> 3) & 1) * 8;
    const int aCol = (lane >> 4) * 4;
    const int bRow = (lane & 7) + (lane >> 4) * 8;
    const int bCol = ((lane >> 3) & 1) * 4;

    const uint32_t smb   = smem_u32(fsm);
    const uint32_t qBase = smb + QP_OFF + (((w * 16 + aRow) * FP + aCol) << 2);
    const uint32_t kBase = smb + KS_OFF + ((bRow * FP + bCol) << 2);
    const uint32_t vBase = smb + VS_OFF + ((bRow * FP + bCol) << 2);

    // 1/sqrt(64) * log2(e): exp2-domain scores
    const float scale = 0.125f * 1.44269504088896340736f;
    const float* qrow = qkv + (size_t)(b * TT) * QKS + h * DD;
    const float* krow = qrow + CC;
    const float* vtrow = qkv + VT_OFF + (size_t)(b * 1024 + h * DD) * TT;

    const int jmax = 2 * qb + 1;

    // ---- prefetch K + Vt block 0 (cp.async, 4 each per thread) ----
#pragma unroll
    for (int t = 0; t < 4; t++) {
        int f = tid + t * 256;
        int row = f >> 4, c4 = f & 15;
        cp_async16(fsm + KS_OFF + row * (FP * 4) + c4 * 16,
                   krow + (size_t)row * QKS + c4 * 4);
        cp_async16(fsm + VS_OFF + row * (FP * 4) + c4 * 16,
                   vtrow + (size_t)row * TT + c4 * 4);
    }
    CP_COMMIT();

    // ---- stage Q tile (128x64), scaled to exp2 domain, re-rounded tf32 ----
#pragma unroll
    for (int t = 0; t < 8; t++) {
        int f   = tid + t * 256;
        int row = f >> 4;
        int c4  = f & 15;
        float4 v = *(const float4*)(qrow + (size_t)(qb * 128 + row) * QKS + c4 * 4);
        float* dst = &Qs[row * FP + c4 * 4];
        dst[0] = to_tf32(v.x * scale); dst[1] = to_tf32(v.y * scale);
        dst[2] = to_tf32(v.z * scale); dst[3] = to_tf32(v.w * scale);
    }
    __syncthreads();

    // ---- hoist Q fragments (loop-invariant) ----
    uint32_t aq[8][4];
#pragma unroll
    for (int kk = 0; kk < 8; kk++)
        ldsm4(aq[kk][0], aq[kk][1], aq[kk][2], aq[kk][3],
              qBase + (uint32_t)(kk * 32));
    // Qs smem now free -> reused as Ps (warp-private rows; no cross-warp hazard)

    float m0 = -1e30f, m1 = -1e30f;
    float l0 = 0.f, l1 = 0.f;
    float o[8][4];
#pragma unroll
    for (int nt = 0; nt < 8; nt++)
#pragma unroll
        for (int i = 0; i < 4; i++) o[nt][i] = 0.f;

    for (int j = 0; j <= jmax; j++) {
        CP_WAIT0();
        __syncthreads();
        if (j + 1 <= jmax) {
            int nb = (j + 1) & 1;
#pragma unroll
            for (int t = 0; t < 4; t++) {
                int f = tid + t * 256;
                int row = f >> 4, c4 = f & 15;
                cp_async16(fsm + KS_OFF + nb * KSTG_B + row * (FP * 4) + c4 * 16,
                           krow + (size_t)((j + 1) * 64 + row) * QKS + c4 * 4);
                cp_async16(fsm + VS_OFF + nb * KSTG_B + row * (FP * 4) + c4 * 16,
                           vtrow + (size_t)row * TT + (j + 1) * 64 + c4 * 4);
            }
            CP_COMMIT();
        }
        const uint32_t kStg = (uint32_t)((j & 1) * KSTG_B);

        // ---- S = Q @ K^T (tf32, exp2 domain): warp computes 16x64 ----
        float s[8][4];
#pragma unroll
        for (int nt = 0; nt < 8; nt++)
#pragma unroll
            for (int i = 0; i < 4; i++) s[nt][i] = 0.f;

#pragma unroll
        for (int kk = 0; kk < 8; kk++) {
            const uint32_t kb4 = (uint32_t)(kk * 32);
            uint32_t bk[4][4];
#pragma unroll
            for (int ng = 0; ng < 4; ng++)
                ldsm4(bk[ng][0], bk[ng][1], bk[ng][2], bk[ng][3],
                      kBase + kStg + kb4 + (uint32_t)(ng * 16 * FP << 2));
#pragma unroll
            for (int ng = 0; ng < 4; ng++) {
                mma8(s[2*ng  ], aq[kk], bk[ng][0], bk[ng][1]);
                mma8(s[2*ng+1], aq[kk], bk[ng][2], bk[ng][3]);
            }
        }

        // ---- causal mask (diagonal-region blocks only) ----
        if (j >= 2 * qb) {
            const int qr0 = qb * 128 + w * 16 + g;
            const int qr1 = qr0 + 8;
            const int jc  = j * 64;
#pragma unroll
            for (int nt = 0; nt < 8; nt++) {
                int c0 = jc + nt * 8 + tir * 2;
                int c1 = c0 + 1;
                if (c0 > qr0) s[nt][0] = -1e30f;
                if (c1 > qr0) s[nt][1] = -1e30f;
                if (c0 > qr1) s[nt][2] = -1e30f;
                if (c1 > qr1) s[nt][3] = -1e30f;
            }
        }

        // ---- online softmax (exp2 domain) ----
        float rm0 = -1e30f, rm1 = -1e30f;
#pragma unroll
        for (int nt = 0; nt < 8; nt++) {
            rm0 = fmaxf(rm0, fmaxf(s[nt][0], s[nt][1]));
            rm1 = fmaxf(rm1, fmaxf(s[nt][2], s[nt][3]));
        }
        rm0 = fmaxf(rm0, __shfl_xor_sync(0xffffffffu, rm0, 1));
        rm0 = fmaxf(rm0, __shfl_xor_sync(0xffffffffu, rm0, 2));
        rm1 = fmaxf(rm1, __shfl_xor_sync(0xffffffffu, rm1, 1));
        rm1 = fmaxf(rm1, __shfl_xor_sync(0xffffffffu, rm1, 2));

        float nm0 = fmaxf(m0, rm0), nm1 = fmaxf(m1, rm1);
        float cf0 = exp2f(m0 - nm0), cf1 = exp2f(m1 - nm1);
        m0 = nm0; m1 = nm1;

        float rs0 = 0.f, rs1 = 0.f;
        const int prow = w * 16 + g;
#pragma unroll
        for (int nt = 0; nt < 8; nt++) {
            int c = nt * 8 + tir * 2;
            float p0 = exp2f(s[nt][0] - nm0);
            float p1 = exp2f(s[nt][1] - nm0);
            float p2 = exp2f(s[nt][2] - nm1);
            float p3 = exp2f(s[nt][3] - nm1);
            rs0 += p0 + p1;
            rs1 += p2 + p3;
            *(float2*)&Qs[(prow    ) * FP + c] =
                make_float2(to_tf32(p0), to_tf32(p1));
            *(float2*)&Qs[(prow + 8) * FP + c] =
                make_float2(to_tf32(p2), to_tf32(p3));
        }
        rs0 += __shfl_xor_sync(0xffffffffu, rs0, 1);
        rs0 += __shfl_xor_sync(0xffffffffu, rs0, 2);
        rs1 += __shfl_xor_sync(0xffffffffu, rs1, 1);
        rs1 += __shfl_xor_sync(0xffffffffu, rs1, 2);
        l0 = l0 * cf0 + rs0;
        l1 = l1 * cf1 + rs1;

#pragma unroll
        for (int nt = 0; nt < 8; nt++) {
            o[nt][0] *= cf0; o[nt][1] *= cf0;
            o[nt][2] *= cf1; o[nt][3] *= cf1;
        }

        __syncwarp();   // Ps rows are per-warp private; order writes vs ldsm

        // ---- O += P @ V  (B-fragments from transposed V via ldmatrix) ----
#pragma unroll
        for (int kk = 0; kk < 8; kk++) {
            const uint32_t kb4 = (uint32_t)(kk * 32);
            uint32_t a[4];
            ldsm4(a[0], a[1], a[2], a[3], qBase + kb4);
            uint32_t bv[4][4];
#pragma unroll
            for (int ng = 0; ng < 4; ng++)
                ldsm4(bv[ng][0], bv[ng][1], bv[ng][2], bv[ng][3],
                      vBase + kStg + kb4 + (uint32_t)(ng * 16 * FP << 2));
#pragma unroll
            for (int ng = 0; ng < 4; ng++) {
                mma8(o[2*ng  ], a, bv[ng][0], bv[ng][1]);
                mma8(o[2*ng+1], a, bv[ng][2], bv[ng][3]);
            }
        }
        __syncthreads();   // all reads done before next stage overwrites
    }

    // ---- normalize, round to tf32 (proj GEMM A operand), write [B,T,C] ----
    const float inv0 = 1.f / l0;
    const float inv1 = 1.f / l1;
    const int t0 = qb * 128 + w * 16 + g;
#pragma unroll
    for (int nt = 0; nt < 8; nt++) {
        int d = nt * 8 + tir * 2;
        float2 v0 = make_float2(to_tf32(o[nt][0] * inv0), to_tf32(o[nt][1] * inv0));
        float2 v1 = make_float2(to_tf32(o[nt][2] * inv1), to_tf32(o[nt][3] * inv1));
        *(float2*)(O + (size_t)(b * TT + t0    ) * CC + h * DD + d) = v0;
        *(float2*)(O + (size_t)(b * TT + t0 + 8) * CC + h * DD + d) = v1;
    }
}

// ---------------------------------------------------------------------------
// Launch
// ---------------------------------------------------------------------------
extern "C" void kernel_launch(void* const* d_in, const int* in_sizes, int n_in,
                              void* d_out, int out_size)
{
    const float* x      = (const float*)d_in[0];
    const float* w_qkv  = (const float*)d_in[1];
    const float* w_proj = (const float*)d_in[2];
    const float* b_proj = (const float*)d_in[3];
    float* out = (float*)d_out;

    cudaFuncSetAttribute(gemm_qkv_kernel,
                         cudaFuncAttributeMaxDynamicSharedMemorySize, GEMM_SMEM);
    cudaFuncSetAttribute(gemm_proj_kernel,
                         cudaFuncAttributeMaxDynamicSharedMemorySize, GEMM_SMEM);
    cudaFuncSetAttribute(flash_kernel,
                         cudaFuncAttributeMaxDynamicSharedMemorySize, FLASH_SMEM);

    // 0) w_qkv -> w_qkv^T in g_att
    transpose_wqkv_kernel<<<dim3(3 * CC / 32, CC / 32), dim3(32, 8)>>>(w_qkv);

    // 1) QKV projection: Q|K -> [4096][2048]; V transposed -> Vt region
    gemm_qkv_kernel<<<dim3(3 * CC / 128, MTOT / 128), 256, GEMM_SMEM>>>(x);

    // 2) Fused causal flash attention: g_qkv -> g_att
    flash_kernel<<<dim3(TT / 128, BB * HH), 256, FLASH_SMEM>>>();

    // 3) w_proj -> w_proj^T into g_qkv[0:1M]
    transpose_wproj_kernel<<<dim3(CC / 32, CC / 32), dim3(32, 8)>>>(w_proj);

    // 4) Output projection + bias: g_att @ w_proj -> out
    gemm_proj_kernel<<<dim3(CC / 128, MTOT / 128), 256, GEMM_SMEM>>>(b_proj, out);
}

// round 12
// speedup vs baseline: 1.3375x; 1.1252x over previous
#include <cuda_runtime.h>
#include <cuda_fp16.h>
#include <cstdint>
#include <cstddef>

// Problem constants
#define BB 2
#define TT 2048
#define CC 1024
#define HH 16
#define DD 64
#define MTOT (BB*TT)          // 4096 rows

// ---------------------------------------------------------------------------
// Scratch: exactly 64 MiB. g_qkv rows [4096][3072 floats]:
//   cols 0..2047  : Q|K (fp32, tf32-rounded)
//   cols 2048+    : V stored as fp16 (1024 halfs = first 2KB of the region)
// Overlays: g_att = w_qkv^T before flash, attention output after;
//           g_qkv[0:1M floats] = w_proj^T after flash.
// ---------------------------------------------------------------------------
__device__ float g_qkv[(size_t)MTOT * 3 * CC];   // 48 MiB
__device__ float g_att[(size_t)MTOT * CC];       // 16 MiB

// ---------------------------------------------------------------------------
// Helpers
// ---------------------------------------------------------------------------
__device__ __forceinline__ float to_tf32(float x) {
    uint32_t y;
    asm("cvt.rna.tf32.f32 %0, %1;" : "=r"(y) : "f"(x));
    return __uint_as_float(y);
}
__device__ __forceinline__ uint32_t cvt_reg(uint32_t r) {
    uint32_t y;
    asm("cvt.rna.tf32.f32 %0, %1;" : "=r"(y) : "f"(__uint_as_float(r)));
    return y;
}

__device__ __forceinline__ void mma8(float d[4], const uint32_t a[4],
                                     uint32_t b0, uint32_t b1) {
    asm volatile(
        "mma.sync.aligned.m16n8k8.row.col.f32.tf32.tf32.f32 "
        "{%0,%1,%2,%3}, {%4,%5,%6,%7}, {%8,%9}, {%0,%1,%2,%3};\n"
        : "+f"(d[0]), "+f"(d[1]), "+f"(d[2]), "+f"(d[3])
        : "r"(a[0]), "r"(a[1]), "r"(a[2]), "r"(a[3]), "r"(b0), "r"(b1));
}

__device__ __forceinline__ void mma16h(float d[4], uint32_t a0, uint32_t a1,
                                       uint32_t a2, uint32_t a3,
                                       uint32_t b0, uint32_t b1) {
    asm volatile(
        "mma.sync.aligned.m16n8k16.row.col.f32.f16.f16.f32 "
        "{%0,%1,%2,%3}, {%4,%5,%6,%7}, {%8,%9}, {%0,%1,%2,%3};\n"
        : "+f"(d[0]), "+f"(d[1]), "+f"(d[2]), "+f"(d[3])
        : "r"(a0), "r"(a1), "r"(a2), "r"(a3), "r"(b0), "r"(b1));
}

__device__ __forceinline__ void ldsm4(uint32_t& r0, uint32_t& r1,
                                      uint32_t& r2, uint32_t& r3, uint32_t addr) {
    asm volatile("ldmatrix.sync.aligned.m8n8.x4.shared.b16 {%0,%1,%2,%3}, [%4];"
                 : "=r"(r0), "=r"(r1), "=r"(r2), "=r"(r3) : "r"(addr));
}
__device__ __forceinline__ void ldsm4t(uint32_t& r0, uint32_t& r1,
                                       uint32_t& r2, uint32_t& r3, uint32_t addr) {
    asm volatile("ldmatrix.sync.aligned.m8n8.x4.trans.shared.b16 {%0,%1,%2,%3}, [%4];"
                 : "=r"(r0), "=r"(r1), "=r"(r2), "=r"(r3) : "r"(addr));
}

__device__ __forceinline__ void cp_async16(void* smem_dst, const void* gsrc) {
    uint32_t s = (uint32_t)__cvta_generic_to_shared(smem_dst);
    asm volatile("cp.async.cg.shared.global [%0], [%1], 16;\n"
                 :: "r"(s), "l"(gsrc) : "memory");
}
#define CP_COMMIT() asm volatile("cp.async.commit_group;\n" ::: "memory")
#define CP_WAIT0()  asm volatile("cp.async.wait_group 0;\n" ::: "memory")

__device__ __forceinline__ uint32_t smem_u32(const void* p) {
    return (uint32_t)__cvta_generic_to_shared(p);
}

__device__ __forceinline__ uint32_t h2(float a, float b) {
    __half2 h = __floats2half2_rn(a, b);
    return *(uint32_t*)&h;
}

// ---------------------------------------------------------------------------
// Transpose + tf32-convert: Wt[n][k] = cvt(W[k][n]).  W is [K][N].
// ---------------------------------------------------------------------------
__device__ __forceinline__ void
transpose_cvt_body(const float* __restrict__ W, float* __restrict__ Wt,
                   int K, int N)
{
    __shared__ float tile[32][33];
    int n0 = blockIdx.x * 32, k0 = blockIdx.y * 32;
    int tx = threadIdx.x, ty = threadIdx.y;
#pragma unroll
    for (int i = 0; i < 4; i++)
        tile[ty + 8 * i][tx] = W[(size_t)(k0 + ty + 8 * i) * N + n0 + tx];
    __syncthreads();
#pragma unroll
    for (int i = 0; i < 4; i++)
        Wt[(size_t)(n0 + ty + 8 * i) * K + k0 + tx] = to_tf32(tile[tx][ty + 8 * i]);
}
__global__ void transpose_wqkv_kernel(const float* __restrict__ w_qkv) {
    transpose_cvt_body(w_qkv, g_att, CC, 3 * CC);
}
__global__ void transpose_wproj_kernel(const float* __restrict__ w_proj) {
    transpose_cvt_body(w_proj, g_qkv, CC, CC);
}

// ---------------------------------------------------------------------------
// tf32 GEMM (R6 core, passing): C = A @ Bt^T (+bias). cp.async 2-stage,
// ldmatrix fragments. 128x128 tile, BK=32, 256 threads.
// QKVOUT: cols<2048 -> fp32 (tf32-rounded); cols>=2048 (V) -> fp16 in place.
// ---------------------------------------------------------------------------
#define GP 36
#define GSTG (128*GP)
#define GEMM_SMEM (4*GSTG*4)   // 73728 B

__device__ __forceinline__ void
gemm_stage(const float* __restrict__ src, float* dst, int K, int k0, int tid)
{
#pragma unroll
    for (int t = 0; t < 4; t++) {
        int f = tid + t * 256;
        int row = f >> 3, c4 = f & 7;
        cp_async16(dst + row * GP + c4 * 4, src + (size_t)row * K + k0 + c4 * 4);
    }
}

template<int ACVT, int ROUND, int HASBIAS, int QKVOUT>
__device__ __forceinline__ void
gemm_body(const float* __restrict__ A, const float* __restrict__ Bt,
          const float* __restrict__ bias, float* __restrict__ C, int N, int K)
{
    extern __shared__ float sm[];
    float* As = sm;
    float* Bs = sm + 2 * GSTG;

    const int tid  = threadIdx.x;
    const int bm   = blockIdx.y;
    const int bn   = blockIdx.x;
    const int warp = tid >> 5;
    const int lane = tid & 31;
    const int wm   = warp & 3;
    const int wn   = warp >> 2;
    const int g    = lane >> 2;
    const int tir  = lane & 3;

    const int aRow = (lane & 7) + ((lane >> 3) & 1) * 8;
    const int aCol = (lane >> 4) * 4;
    const int bRow = (lane & 7) + (lane >> 4) * 8;
    const int bCol = ((lane >> 3) & 1) * 4;

    const uint32_t aBase = smem_u32(As) + (((wm * 32 + aRow) * GP + aCol) << 2);
    const uint32_t bBase = smem_u32(Bs) + (((wn * 64 + bRow) * GP + bCol) << 2);

    float acc[2][8][4];
#pragma unroll
    for (int mt = 0; mt < 2; mt++)
#pragma unroll
        for (int nt = 0; nt < 8; nt++)
#pragma unroll
            for (int i = 0; i < 4; i++) acc[mt][nt][i] = 0.0f;

    const float* Ablk = A  + (size_t)(bm * 128) * K;
    const float* Bblk = Bt + (size_t)(bn * 128) * K;
    const int NT = K >> 5;

    gemm_stage(Ablk, As, K, 0, tid);
    gemm_stage(Bblk, Bs, K, 0, tid);
    CP_COMMIT();

    for (int it = 0; it < NT; it++) {
        CP_WAIT0();
        __syncthreads();
        if (it + 1 < NT) {
            int nb = (it + 1) & 1;
            gemm_stage(Ablk, As + nb * GSTG, K, (it + 1) * 32, tid);
            gemm_stage(Bblk, Bs + nb * GSTG, K, (it + 1) * 32, tid);
            CP_COMMIT();
        }
        const uint32_t stg = (uint32_t)((it & 1) * GSTG * 4);

#pragma unroll
        for (int kk = 0; kk < 4; kk++) {
            const uint32_t kb4 = (uint32_t)(kk * 8 * 4);
            uint32_t a[2][4];
            ldsm4(a[0][0], a[0][1], a[0][2], a[0][3], aBase + stg + kb4);
            ldsm4(a[1][0], a[1][1], a[1][2], a[1][3],
                  aBase + stg + kb4 + (16 * GP << 2));
            if (ACVT) {
#pragma unroll
                for (int mt = 0; mt < 2; mt++)
#pragma unroll
                    for (int i = 0; i < 4; i++) a[mt][i] = cvt_reg(a[mt][i]);
            }
            uint32_t b[4][4];
#pragma unroll
            for (int ng = 0; ng < 4; ng++)
                ldsm4(b[ng][0], b[ng][1], b[ng][2], b[ng][3],
                      bBase + stg + kb4 + (uint32_t)(ng * 16 * GP << 2));
#pragma unroll
            for (int ng = 0; ng < 4; ng++) {
                mma8(acc[0][2*ng  ], a[0], b[ng][0], b[ng][1]);
                mma8(acc[0][2*ng+1], a[0], b[ng][2], b[ng][3]);
                mma8(acc[1][2*ng  ], a[1], b[ng][0], b[ng][1]);
                mma8(acc[1][2*ng+1], a[1], b[ng][2], b[ng][3]);
            }
        }
        __syncthreads();
    }

#pragma unroll
    for (int mt = 0; mt < 2; mt++) {
#pragma unroll
        for (int nt = 0; nt < 8; nt++) {
            int row = bm * 128 + wm * 32 + mt * 16 + g;
            int col = bn * 128 + wn * 64 + nt * 8 + tir * 2;
            float bb0 = 0.f, bb1 = 0.f;
            if (HASBIAS) { bb0 = bias[col]; bb1 = bias[col + 1]; }
            float v00 = acc[mt][nt][0] + bb0, v01 = acc[mt][nt][1] + bb1;
            float v10 = acc[mt][nt][2] + bb0, v11 = acc[mt][nt][3] + bb1;
            if (QKVOUT && col >= 2 * CC) {
                // V third: fp16 in place (flash consumes fp16)
                __half2 h0 = __floats2half2_rn(v00, v01);
                __half2 h1 = __floats2half2_rn(v10, v11);
                char* base = (char*)C;
                *(__half2*)(base + (size_t)row * (N * 4) + 2 * CC * 4
                            + (col - 2 * CC) * 2) = h0;
                *(__half2*)(base + (size_t)(row + 8) * (N * 4) + 2 * CC * 4
                            + (col - 2 * CC) * 2) = h1;
            } else {
                if (ROUND) {
                    v00 = to_tf32(v00); v01 = to_tf32(v01);
                    v10 = to_tf32(v10); v11 = to_tf32(v11);
                }
                *(float2*)(C + (size_t)row * N + col)       = make_float2(v00, v01);
                *(float2*)(C + (size_t)(row + 8) * N + col) = make_float2(v10, v11);
            }
        }
    }
}

__global__ void __launch_bounds__(256, 2)
gemm_qkv_kernel(const float* __restrict__ x)
{
    gemm_body<1, 1, 0, 1>(x, g_att, nullptr, g_qkv, 3 * CC, CC);
}
__global__ void __launch_bounds__(256, 2)
gemm_proj_kernel(const float* __restrict__ b_proj, float* __restrict__ out)
{
    gemm_body<0, 0, 1, 0>(g_att, g_qkv, b_proj, out, CC, CC);
}

// ---------------------------------------------------------------------------
// Flash attention (causal). QK in tf32 (exp2 domain), PV in fp16 m16n8k16.
// FA2 register trick: softmax C-fragment == PV A-fragment for fp16, so P is
// converted in registers (half2) and NEVER stored to smem. V staged fp16 via
// cp.async (double-buffered); B-fragments via ldmatrix.trans. Q fragments
// hoisted. smem 88064 B -> 2 CTAs/SM. grid=(T/128, B*H), 8 warps.
// ---------------------------------------------------------------------------
#define FP 68
#define VSB 144                            // V smem row pitch (bytes)
#define QS_OFF 0                           // 128 x FP floats (Q staging only)
#define KS_OFF (128*FP*4)                  // 34816
#define KSTG_B (64*FP*4)                   // 17408
#define VS_OFF (KS_OFF + 2*KSTG_B)         // 69632
#define VSTG_B (64*VSB)                    // 9216
#define FLASH_SMEM (VS_OFF + 2*VSTG_B)     // 88064

__global__ void __launch_bounds__(256, 2)
flash_kernel()
{
    extern __shared__ char fsm[];
    float* Qs = (float*)(fsm + QS_OFF);

    const float* qkv = g_qkv;
    float* O = g_att;

    const int qb  = (gridDim.x - 1) - blockIdx.x;   // heavy blocks first
    const int bh  = blockIdx.y;
    const int b   = bh >> 4;
    const int h   = bh & 15;
    const int tid = threadIdx.x;
    const int w   = tid >> 5;
    const int lane = tid & 31;
    const int g   = lane >> 2;
    const int tir = lane & 3;

    const int aRow = (lane & 7) + ((lane >> 3) & 1) * 8;
    const int aCol = (lane >> 4) * 4;
    const int bRow = (lane & 7) + (lane >> 4) * 8;
    const int bCol = ((lane >> 3) & 1) * 4;

    const uint32_t smb   = smem_u32(fsm);
    const uint32_t qBase = smb + QS_OFF + (((w * 16 + aRow) * FP + aCol) << 2);
    const uint32_t kBase = smb + KS_OFF + ((bRow * FP + bCol) << 2);
    // PV B-fragment (ldmatrix.trans on fp16 V rows [t][d]):
    const uint32_t vBase = smb + VS_OFF
                         + ((lane & 7) + 8 * ((lane >> 3) & 1)) * VSB
                         + (lane >> 4) * 16;

    // 1/sqrt(64) * log2(e): exp2-domain scores
    const float scale = 0.125f * 1.44269504088896340736f;
    const float* qrow = qkv + (size_t)(b * TT) * 3 * CC + h * DD;
    const float* krow = qrow + CC;
    const char*  vrow = (const char*)qkv + (size_t)(b * TT) * (3 * CC * 4)
                      + 2 * CC * 4 + h * DD * 2;   // fp16 V region

    const int jmax = 2 * qb + 1;

    // ---- prefetch K + V block 0 ----
#pragma unroll
    for (int t = 0; t < 4; t++) {
        int f = tid + t * 256;
        int row = f >> 4, c4 = f & 15;
        cp_async16(fsm + KS_OFF + row * (FP * 4) + c4 * 16,
                   krow + (size_t)row * 3 * CC + c4 * 4);
    }
#pragma unroll
    for (int t = 0; t < 2; t++) {
        int f = tid + t * 256;
        int row = f >> 3, ch = f & 7;
        cp_async16(fsm + VS_OFF + row * VSB + ch * 16,
                   vrow + (size_t)row * (3 * CC * 4) + ch * 16);
    }
    CP_COMMIT();

    // ---- stage Q tile (128x64), scaled to exp2 domain, re-rounded tf32 ----
#pragma unroll
    for (int t = 0; t < 8; t++) {
        int f   = tid + t * 256;
        int row = f >> 4;
        int c4  = f & 15;
        float4 v = *(const float4*)(qrow + (size_t)(qb * 128 + row) * 3 * CC + c4 * 4);
        float* dst = &Qs[row * FP + c4 * 4];
        dst[0] = to_tf32(v.x * scale); dst[1] = to_tf32(v.y * scale);
        dst[2] = to_tf32(v.z * scale); dst[3] = to_tf32(v.w * scale);
    }
    __syncthreads();

    // ---- hoist Q fragments (loop-invariant) ----
    uint32_t aq[8][4];
#pragma unroll
    for (int kk = 0; kk < 8; kk++)
        ldsm4(aq[kk][0], aq[kk][1], aq[kk][2], aq[kk][3],
              qBase + (uint32_t)(kk * 32));

    float m0 = -1e30f, m1 = -1e30f;
    float l0 = 0.f, l1 = 0.f;
    float o[8][4];
#pragma unroll
    for (int nt = 0; nt < 8; nt++)
#pragma unroll
        for (int i = 0; i < 4; i++) o[nt][i] = 0.f;

    for (int j = 0; j <= jmax; j++) {
        CP_WAIT0();
        __syncthreads();
        if (j + 1 <= jmax) {
            int nb = (j + 1) & 1;
#pragma unroll
            for (int t = 0; t < 4; t++) {
                int f = tid + t * 256;
                int row = f >> 4, c4 = f & 15;
                cp_async16(fsm + KS_OFF + nb * KSTG_B + row * (FP * 4) + c4 * 16,
                           krow + (size_t)((j + 1) * 64 + row) * 3 * CC + c4 * 4);
            }
#pragma unroll
            for (int t = 0; t < 2; t++) {
                int f = tid + t * 256;
                int row = f >> 3, ch = f & 7;
                cp_async16(fsm + VS_OFF + nb * VSTG_B + row * VSB + ch * 16,
                           vrow + (size_t)((j + 1) * 64 + row) * (3 * CC * 4) + ch * 16);
            }
            CP_COMMIT();
        }
        const uint32_t kStg = (uint32_t)((j & 1) * KSTG_B);
        const uint32_t vStg = (uint32_t)((j & 1) * VSTG_B);

        // ---- S = Q @ K^T (tf32, exp2 domain): warp computes 16x64 ----
        float s[8][4];
#pragma unroll
        for (int nt = 0; nt < 8; nt++)
#pragma unroll
            for (int i = 0; i < 4; i++) s[nt][i] = 0.f;

#pragma unroll
        for (int kk = 0; kk < 8; kk++) {
            const uint32_t kb4 = (uint32_t)(kk * 32);
            uint32_t bk[4][4];
#pragma unroll
            for (int ng = 0; ng < 4; ng++)
                ldsm4(bk[ng][0], bk[ng][1], bk[ng][2], bk[ng][3],
                      kBase + kStg + kb4 + (uint32_t)(ng * 16 * FP << 2));
#pragma unroll
            for (int ng = 0; ng < 4; ng++) {
                mma8(s[2*ng  ], aq[kk], bk[ng][0], bk[ng][1]);
                mma8(s[2*ng+1], aq[kk], bk[ng][2], bk[ng][3]);
            }
        }

        // ---- causal mask (diagonal-region blocks only) ----
        if (j >= 2 * qb) {
            const int qr0 = qb * 128 + w * 16 + g;
            const int qr1 = qr0 + 8;
            const int jc  = j * 64;
#pragma unroll
            for (int nt = 0; nt < 8; nt++) {
                int c0 = jc + nt * 8 + tir * 2;
                int c1 = c0 + 1;
                if (c0 > qr0) s[nt][0] = -1e30f;
                if (c1 > qr0) s[nt][1] = -1e30f;
                if (c0 > qr1) s[nt][2] = -1e30f;
                if (c1 > qr1) s[nt][3] = -1e30f;
            }
        }

        // ---- online softmax (exp2 domain) ----
        float rm0 = -1e30f, rm1 = -1e30f;
#pragma unroll
        for (int nt = 0; nt < 8; nt++) {
            rm0 = fmaxf(rm0, fmaxf(s[nt][0], s[nt][1]));
            rm1 = fmaxf(rm1, fmaxf(s[nt][2], s[nt][3]));
        }
        rm0 = fmaxf(rm0, __shfl_xor_sync(0xffffffffu, rm0, 1));
        rm0 = fmaxf(rm0, __shfl_xor_sync(0xffffffffu, rm0, 2));
        rm1 = fmaxf(rm1, __shfl_xor_sync(0xffffffffu, rm1, 1));
        rm1 = fmaxf(rm1, __shfl_xor_sync(0xffffffffu, rm1, 2));

        float nm0 = fmaxf(m0, rm0), nm1 = fmaxf(m1, rm1);
        float cf0 = exp2f(m0 - nm0), cf1 = exp2f(m1 - nm1);
        m0 = nm0; m1 = nm1;

        // P in registers as half2 A-fragments (FA2 trick):
        // phA[nt] = (row g,   cols nt*8+2tir, +1), phB[nt] = (row g+8, same)
        uint32_t phA[8], phB[8];
        float rs0 = 0.f, rs1 = 0.f;
#pragma unroll
        for (int nt = 0; nt < 8; nt++) {
            float p0 = exp2f(s[nt][0] - nm0);
            float p1 = exp2f(s[nt][1] - nm0);
            float p2 = exp2f(s[nt][2] - nm1);
            float p3 = exp2f(s[nt][3] - nm1);
            rs0 += p0 + p1;
            rs1 += p2 + p3;
            phA[nt] = h2(p0, p1);
            phB[nt] = h2(p2, p3);
        }
        rs0 += __shfl_xor_sync(0xffffffffu, rs0, 1);
        rs0 += __shfl_xor_sync(0xffffffffu, rs0, 2);
        rs1 += __shfl_xor_sync(0xffffffffu, rs1, 1);
        rs1 += __shfl_xor_sync(0xffffffffu, rs1, 2);
        l0 = l0 * cf0 + rs0;
        l1 = l1 * cf1 + rs1;

#pragma unroll
        for (int nt = 0; nt < 8; nt++) {
            o[nt][0] *= cf0; o[nt][1] *= cf0;
            o[nt][2] *= cf1; o[nt][3] *= cf1;
        }

        // ---- O += P @ V  (fp16 m16n8k16; A from registers, B ldsm.trans) ----
#pragma unroll
        for (int kk = 0; kk < 4; kk++) {
            const uint32_t vk = vBase + vStg + (uint32_t)(kk * 16 * VSB);
#pragma unroll
            for (int ng = 0; ng < 4; ng++) {
                uint32_t bv[4];
                ldsm4t(bv[0], bv[1], bv[2], bv[3], vk + (uint32_t)(ng * 32));
                mma16h(o[2*ng  ], phA[2*kk], phB[2*kk],
                       phA[2*kk+1], phB[2*kk+1], bv[0], bv[1]);
                mma16h(o[2*ng+1], phA[2*kk], phB[2*kk],
                       phA[2*kk+1], phB[2*kk+1], bv[2], bv[3]);
            }
        }
        __syncthreads();   // all smem reads done before next stage overwrites
    }

    // ---- normalize, round to tf32 (proj GEMM A operand), write [B,T,C] ----
    const float inv0 = 1.f / l0;
    const float inv1 = 1.f / l1;
    const int t0 = qb * 128 + w * 16 + g;
#pragma unroll
    for (int nt = 0; nt < 8; nt++) {
        int d = nt * 8 + tir * 2;
        float2 v0 = make_float2(to_tf32(o[nt][0] * inv0), to_tf32(o[nt][1] * inv0));
        float2 v1 = make_float2(to_tf32(o[nt][2] * inv1), to_tf32(o[nt][3] * inv1));
        *(float2*)(O + (size_t)(b * TT + t0    ) * CC + h * DD + d) = v0;
        *(float2*)(O + (size_t)(b * TT + t0 + 8) * CC + h * DD + d) = v1;
    }
}

// ---------------------------------------------------------------------------
// Launch
// ---------------------------------------------------------------------------
extern "C" void kernel_launch(void* const* d_in, const int* in_sizes, int n_in,
                              void* d_out, int out_size)
{
    const float* x      = (const float*)d_in[0];
    const float* w_qkv  = (const float*)d_in[1];
    const float* w_proj = (const float*)d_in[2];
    const float* b_proj = (const float*)d_in[3];
    float* out = (float*)d_out;

    cudaFuncSetAttribute(gemm_qkv_kernel,
                         cudaFuncAttributeMaxDynamicSharedMemorySize, GEMM_SMEM);
    cudaFuncSetAttribute(gemm_proj_kernel,
                         cudaFuncAttributeMaxDynamicSharedMemorySize, GEMM_SMEM);
    cudaFuncSetAttribute(flash_kernel,
                         cudaFuncAttributeMaxDynamicSharedMemorySize, FLASH_SMEM);

    // 0) w_qkv -> w_qkv^T in g_att
    transpose_wqkv_kernel<<<dim3(3 * CC / 32, CC / 32), dim3(32, 8)>>>(w_qkv);

    // 1) QKV projection: Q,K tf32-rounded fp32; V stored fp16 in place
    gemm_qkv_kernel<<<dim3(3 * CC / 128, MTOT / 128), 256, GEMM_SMEM>>>(x);

    // 2) Fused causal flash attention: g_qkv -> g_att
    flash_kernel<<<dim3(TT / 128, BB * HH), 256, FLASH_SMEM>>>();

    // 3) w_proj -> w_proj^T into g_qkv[0:1M]
    transpose_wproj_kernel<<<dim3(CC / 32, CC / 32), dim3(32, 8)>>>(w_proj);

    // 4) Output projection + bias: g_att @ w_proj -> out
    gemm_proj_kernel<<<dim3(CC / 128, MTOT / 128), 256, GEMM_SMEM>>>(b_proj, out);
}

// round 13
// speedup vs baseline: 2.0747x; 1.5511x over previous
#include <cuda_runtime.h>
#include <cuda_fp16.h>
#include <cstdint>
#include <cstddef>

// Problem constants
#define BB 2
#define TT 2048
#define CC 1024
#define HH 16
#define DD 64
#define MTOT (BB*TT)          // 4096 rows

// 0.125 * log2(e): folded into Q at the QKV epilogue (exp2-domain softmax)
#define QSC 0.1803368801111204f

// ---------------------------------------------------------------------------
// Scratch: exactly 64 MiB (proven footprint), all-fp16 data plan:
//   g_qkv float[12M]:
//     half view [0 : 6M floats)  = QKV output [4096][3072 halfs] (Q pre-scaled)
//     [6M : 8M floats)           = x_fp16 [4096][1024 halfs]; after flash this
//                                  region is dead -> reused for w_proj^T fp16
//   g_att float[4M]:
//     half view = w_qkv^T fp16 [3072][1024] before flash (6 MiB);
//                 attention out fp16 [4096][1024] after flash (8 MiB)
// ---------------------------------------------------------------------------
__device__ float g_qkv[(size_t)MTOT * 3 * CC];   // 48 MiB
__device__ float g_att[(size_t)MTOT * CC];       // 16 MiB
#define XH_FOFF  6291456                          // float offset of x_fp16/wprojT

// ---------------------------------------------------------------------------
// Helpers
// ---------------------------------------------------------------------------
__device__ __forceinline__ void mma16h(float d[4], uint32_t a0, uint32_t a1,
                                       uint32_t a2, uint32_t a3,
                                       uint32_t b0, uint32_t b1) {
    asm volatile(
        "mma.sync.aligned.m16n8k16.row.col.f32.f16.f16.f32 "
        "{%0,%1,%2,%3}, {%4,%5,%6,%7}, {%8,%9}, {%0,%1,%2,%3};\n"
        : "+f"(d[0]), "+f"(d[1]), "+f"(d[2]), "+f"(d[3])
        : "r"(a0), "r"(a1), "r"(a2), "r"(a3), "r"(b0), "r"(b1));
}

__device__ __forceinline__ void ldsm4(uint32_t& r0, uint32_t& r1,
                                      uint32_t& r2, uint32_t& r3, uint32_t addr) {
    asm volatile("ldmatrix.sync.aligned.m8n8.x4.shared.b16 {%0,%1,%2,%3}, [%4];"
                 : "=r"(r0), "=r"(r1), "=r"(r2), "=r"(r3) : "r"(addr));
}
__device__ __forceinline__ void ldsm4t(uint32_t& r0, uint32_t& r1,
                                       uint32_t& r2, uint32_t& r3, uint32_t addr) {
    asm volatile("ldmatrix.sync.aligned.m8n8.x4.trans.shared.b16 {%0,%1,%2,%3}, [%4];"
                 : "=r"(r0), "=r"(r1), "=r"(r2), "=r"(r3) : "r"(addr));
}

__device__ __forceinline__ void cp_async16(void* smem_dst, const void* gsrc) {
    uint32_t s = (uint32_t)__cvta_generic_to_shared(smem_dst);
    asm volatile("cp.async.cg.shared.global [%0], [%1], 16;\n"
                 :: "r"(s), "l"(gsrc) : "memory");
}
#define CP_COMMIT() asm volatile("cp.async.commit_group;\n" ::: "memory")
#define CP_WAIT0()  asm volatile("cp.async.wait_group 0;\n" ::: "memory")

__device__ __forceinline__ uint32_t smem_u32(const void* p) {
    return (uint32_t)__cvta_generic_to_shared(p);
}
__device__ __forceinline__ uint32_t h2(float a, float b) {
    __half2 h = __floats2half2_rn(a, b);
    return *(uint32_t*)&h;
}

// ---------------------------------------------------------------------------
// Prep: x -> fp16; W[k][n] -> Wt[n][k] fp16
// ---------------------------------------------------------------------------
__global__ void cvt_x_kernel(const float* __restrict__ x) {
    size_t i = (size_t)blockIdx.x * 256 + threadIdx.x;
    float4 v = ((const float4*)x)[i];
    __half2* dst = (__half2*)(g_qkv + XH_FOFF) + i * 2;
    dst[0] = __floats2half2_rn(v.x, v.y);
    dst[1] = __floats2half2_rn(v.z, v.w);
}

__device__ __forceinline__ void
transpose_cvt_h(const float* __restrict__ W, __half* __restrict__ Wt,
                int K, int N)
{
    __shared__ float tile[32][33];
    int n0 = blockIdx.x * 32, k0 = blockIdx.y * 32;
    int tx = threadIdx.x, ty = threadIdx.y;
#pragma unroll
    for (int i = 0; i < 4; i++)
        tile[ty + 8 * i][tx] = W[(size_t)(k0 + ty + 8 * i) * N + n0 + tx];
    __syncthreads();
#pragma unroll
    for (int i = 0; i < 4; i++)
        Wt[(size_t)(n0 + ty + 8 * i) * K + k0 + tx] =
            __float2half_rn(tile[tx][ty + 8 * i]);
}
__global__ void transpose_wqkv_kernel(const float* __restrict__ w_qkv) {
    transpose_cvt_h(w_qkv, (__half*)g_att, CC, 3 * CC);
}
__global__ void transpose_wproj_kernel(const float* __restrict__ w_proj) {
    transpose_cvt_h(w_proj, (__half*)(g_qkv + XH_FOFF), CC, CC);
}

// ---------------------------------------------------------------------------
// fp16 GEMM: C[M,N] = A[M,K] @ Bt[N,K]^T. 128x128 tile, BK=32 halfs,
// 256 threads (8 warps = 4m x 2n). cp.async 2-stage, ldmatrix frags,
// m16n8k16 fp16 mma (fp32 accum).
// OUTMODE 0: fp32 out + bias (proj). OUTMODE 1: fp16 out, Q cols scaled (QKV).
// ---------------------------------------------------------------------------
#define GPH 40                     // smem pitch in halfs (80 B): conflict-free
#define GSTGH (128*GPH)            // halfs per operand-stage
#define GEMM_SMEM (4*GSTGH*2)      // 40960 B

__device__ __forceinline__ void
gemm_stage_h(const __half* __restrict__ src, __half* dst, int K, int k0, int tid)
{
#pragma unroll
    for (int t = 0; t < 2; t++) {
        int f = tid + t * 256;
        int row = f >> 2, ch = f & 3;
        cp_async16(dst + row * GPH + ch * 8, src + (size_t)row * K + k0 + ch * 8);
    }
}

template<int OUTMODE>
__device__ __forceinline__ void
gemm_body_h(const __half* __restrict__ A, const __half* __restrict__ Bt,
            const float* __restrict__ bias, void* Cout, int N, int K)
{
    extern __shared__ char smc[];
    __half* As = (__half*)smc;
    __half* Bs = As + 2 * GSTGH;

    const int tid  = threadIdx.x;
    const int bm   = blockIdx.y;
    const int bn   = blockIdx.x;
    const int warp = tid >> 5;
    const int lane = tid & 31;
    const int wm   = warp & 3;
    const int wn   = warp >> 2;
    const int g    = lane >> 2;
    const int tir  = lane & 3;

    const int aRow = (lane & 7) + ((lane >> 3) & 1) * 8;
    const int aColH = (lane >> 4) * 8;
    const int bRow = (lane & 7) + (lane >> 4) * 8;
    const int bColH = ((lane >> 3) & 1) * 8;

    const uint32_t aBase = smem_u32(As) + (((wm * 32 + aRow) * GPH + aColH) << 1);
    const uint32_t bBase = smem_u32(Bs) + (((wn * 64 + bRow) * GPH + bColH) << 1);

    float acc[2][8][4];
#pragma unroll
    for (int mt = 0; mt < 2; mt++)
#pragma unroll
        for (int nt = 0; nt < 8; nt++)
#pragma unroll
            for (int i = 0; i < 4; i++) acc[mt][nt][i] = 0.0f;

    const __half* Ablk = A  + (size_t)(bm * 128) * K;
    const __half* Bblk = Bt + (size_t)(bn * 128) * K;
    const int NT = K >> 5;   // 32

    gemm_stage_h(Ablk, As, K, 0, tid);
    gemm_stage_h(Bblk, Bs, K, 0, tid);
    CP_COMMIT();

    for (int it = 0; it < NT; it++) {
        CP_WAIT0();
        __syncthreads();
        if (it + 1 < NT) {
            int nb = (it + 1) & 1;
            gemm_stage_h(Ablk, As + nb * GSTGH, K, (it + 1) * 32, tid);
            gemm_stage_h(Bblk, Bs + nb * GSTGH, K, (it + 1) * 32, tid);
            CP_COMMIT();
        }
        const uint32_t stg = (uint32_t)((it & 1) * GSTGH * 2);

#pragma unroll
        for (int kk = 0; kk < 2; kk++) {
            const uint32_t kb = (uint32_t)(kk * 32);   // 16 halfs
            uint32_t a[2][4];
            ldsm4(a[0][0], a[0][1], a[0][2], a[0][3], aBase + stg + kb);
            ldsm4(a[1][0], a[1][1], a[1][2], a[1][3],
                  aBase + stg + kb + (16 * GPH << 1));
            uint32_t b[4][4];
#pragma unroll
            for (int ng = 0; ng < 4; ng++)
                ldsm4(b[ng][0], b[ng][1], b[ng][2], b[ng][3],
                      bBase + stg + kb + (uint32_t)(ng * 16 * GPH << 1));
#pragma unroll
            for (int ng = 0; ng < 4; ng++) {
                mma16h(acc[0][2*ng  ], a[0][0], a[0][1], a[0][2], a[0][3],
                       b[ng][0], b[ng][1]);
                mma16h(acc[0][2*ng+1], a[0][0], a[0][1], a[0][2], a[0][3],
                       b[ng][2], b[ng][3]);
                mma16h(acc[1][2*ng  ], a[1][0], a[1][1], a[1][2], a[1][3],
                       b[ng][0], b[ng][1]);
                mma16h(acc[1][2*ng+1], a[1][0], a[1][1], a[1][2], a[1][3],
                       b[ng][2], b[ng][3]);
            }
        }
        __syncthreads();
    }

    // ---- epilogue ----
#pragma unroll
    for (int mt = 0; mt < 2; mt++) {
#pragma unroll
        for (int nt = 0; nt < 8; nt++) {
            int row = bm * 128 + wm * 32 + mt * 16 + g;
            int col = bn * 128 + wn * 64 + nt * 8 + tir * 2;
            float v00 = acc[mt][nt][0], v01 = acc[mt][nt][1];
            float v10 = acc[mt][nt][2], v11 = acc[mt][nt][3];
            if (OUTMODE == 0) {
                float bb0 = bias[col], bb1 = bias[col + 1];
                float* Cf = (float*)Cout;
                *(float2*)(Cf + (size_t)row * N + col) =
                    make_float2(v00 + bb0, v01 + bb1);
                *(float2*)(Cf + (size_t)(row + 8) * N + col) =
                    make_float2(v10 + bb1 * 0.f + v10 * 0.f + (acc[mt][nt][2] + bb0),
                                v11 + bb1) ;
            } else {
                if (col < CC) { v00 *= QSC; v01 *= QSC; v10 *= QSC; v11 *= QSC; }
                __half* Ch = (__half*)Cout;
                *(__half2*)(Ch + (size_t)row * (3 * CC) + col) =
                    __floats2half2_rn(v00, v01);
                *(__half2*)(Ch + (size_t)(row + 8) * (3 * CC) + col) =
                    __floats2half2_rn(v10, v11);
            }
        }
    }
}

// NOTE: the OUTMODE==0 branch above had a transcription hazard; define it
// cleanly via a dedicated epilogue-correct instantiation below.

template<>
__device__ __forceinline__ void
gemm_body_h<2>(const __half* __restrict__ A, const __half* __restrict__ Bt,
               const float* __restrict__ bias, void* Cout, int N, int K)
{
    // unused specialization guard
}

__global__ void __launch_bounds__(256, 2)
gemm_qkv_kernel()
{
    gemm_body_h<1>((const __half*)(g_qkv + XH_FOFF), (const __half*)g_att,
                   nullptr, (void*)g_qkv, 3 * CC, CC);
}

// Proj GEMM with a clean fp32+bias epilogue (no template branch tricks)
__global__ void __launch_bounds__(256, 2)
gemm_proj_kernel(const float* __restrict__ b_proj, float* __restrict__ out)
{
    extern __shared__ char smc[];
    __half* As = (__half*)smc;
    __half* Bs = As + 2 * GSTGH;
    const __half* A  = (const __half*)g_att;
    const __half* Bt = (const __half*)(g_qkv + XH_FOFF);
    const int N = CC, K = CC;

    const int tid  = threadIdx.x;
    const int bm   = blockIdx.y;
    const int bn   = blockIdx.x;
    const int warp = tid >> 5;
    const int lane = tid & 31;
    const int wm   = warp & 3;
    const int wn   = warp >> 2;
    const int g    = lane >> 2;
    const int tir  = lane & 3;

    const int aRow = (lane & 7) + ((lane >> 3) & 1) * 8;
    const int aColH = (lane >> 4) * 8;
    const int bRow = (lane & 7) + (lane >> 4) * 8;
    const int bColH = ((lane >> 3) & 1) * 8;

    const uint32_t aBase = smem_u32(As) + (((wm * 32 + aRow) * GPH + aColH) << 1);
    const uint32_t bBase = smem_u32(Bs) + (((wn * 64 + bRow) * GPH + bColH) << 1);

    float acc[2][8][4];
#pragma unroll
    for (int mt = 0; mt < 2; mt++)
#pragma unroll
        for (int nt = 0; nt < 8; nt++)
#pragma unroll
            for (int i = 0; i < 4; i++) acc[mt][nt][i] = 0.0f;

    const __half* Ablk = A  + (size_t)(bm * 128) * K;
    const __half* Bblk = Bt + (size_t)(bn * 128) * K;
    const int NT = K >> 5;

    gemm_stage_h(Ablk, As, K, 0, tid);
    gemm_stage_h(Bblk, Bs, K, 0, tid);
    CP_COMMIT();

    for (int it = 0; it < NT; it++) {
        CP_WAIT0();
        __syncthreads();
        if (it + 1 < NT) {
            int nb = (it + 1) & 1;
            gemm_stage_h(Ablk, As + nb * GSTGH, K, (it + 1) * 32, tid);
            gemm_stage_h(Bblk, Bs + nb * GSTGH, K, (it + 1) * 32, tid);
            CP_COMMIT();
        }
        const uint32_t stg = (uint32_t)((it & 1) * GSTGH * 2);

#pragma unroll
        for (int kk = 0; kk < 2; kk++) {
            const uint32_t kb = (uint32_t)(kk * 32);
            uint32_t a[2][4];
            ldsm4(a[0][0], a[0][1], a[0][2], a[0][3], aBase + stg + kb);
            ldsm4(a[1][0], a[1][1], a[1][2], a[1][3],
                  aBase + stg + kb + (16 * GPH << 1));
            uint32_t b[4][4];
#pragma unroll
            for (int ng = 0; ng < 4; ng++)
                ldsm4(b[ng][0], b[ng][1], b[ng][2], b[ng][3],
                      bBase + stg + kb + (uint32_t)(ng * 16 * GPH << 1));
#pragma unroll
            for (int ng = 0; ng < 4; ng++) {
                mma16h(acc[0][2*ng  ], a[0][0], a[0][1], a[0][2], a[0][3],
                       b[ng][0], b[ng][1]);
                mma16h(acc[0][2*ng+1], a[0][0], a[0][1], a[0][2], a[0][3],
                       b[ng][2], b[ng][3]);
                mma16h(acc[1][2*ng  ], a[1][0], a[1][1], a[1][2], a[1][3],
                       b[ng][0], b[ng][1]);
                mma16h(acc[1][2*ng+1], a[1][0], a[1][1], a[1][2], a[1][3],
                       b[ng][2], b[ng][3]);
            }
        }
        __syncthreads();
    }

#pragma unroll
    for (int mt = 0; mt < 2; mt++) {
#pragma unroll
        for (int nt = 0; nt < 8; nt++) {
            int row = bm * 128 + wm * 32 + mt * 16 + g;
            int col = bn * 128 + wn * 64 + nt * 8 + tir * 2;
            float bb0 = b_proj[col], bb1 = b_proj[col + 1];
            *(float2*)(out + (size_t)row * N + col) =
                make_float2(acc[mt][nt][0] + bb0, acc[mt][nt][1] + bb1);
            *(float2*)(out + (size_t)(row + 8) * N + col) =
                make_float2(acc[mt][nt][2] + bb0, acc[mt][nt][3] + bb1);
        }
    }
}

// ---------------------------------------------------------------------------
// Flash attention (causal), all-fp16 MMA (m16n8k16, fp32 accum/softmax).
// Q pre-scaled by 0.125*log2e in the QKV epilogue -> exp2-domain scores.
// S: Q frags hoisted (aq[4][4]), K B-frags via ldsm4 (k-major rows).
// P: FA2 register trick (C-frag == A-frag). PV: V fp16, ldsm4t (R12-validated).
// smem 55296 B -> 2 CTAs/SM. grid=(T/128, B*H), 8 warps.
// ---------------------------------------------------------------------------
#define QPH 72                             // Q/K smem pitch in halfs (144 B)
#define VSB 144                            // V smem row pitch (bytes)
#define QS_OFF 0                           // 128 x QPH halfs
#define KS_OFF (128*QPH*2)                 // 18432
#define KSTG_B (64*QPH*2)                  // 9216
#define VS_OFF (KS_OFF + 2*KSTG_B)         // 36864
#define VSTG_B (64*VSB)                    // 9216
#define FLASH_SMEM (VS_OFF + 2*VSTG_B)     // 55296

__global__ void __launch_bounds__(256, 2)
flash_kernel()
{
    extern __shared__ char fsm[];
    __half* Qs = (__half*)(fsm + QS_OFF);

    const __half* qkvh = (const __half*)g_qkv;
    __half* O = (__half*)g_att;

    const int qb  = (gridDim.x - 1) - blockIdx.x;   // heavy blocks first
    const int bh  = blockIdx.y;
    const int b   = bh >> 4;
    const int h   = bh & 15;
    const int tid = threadIdx.x;
    const int w   = tid >> 5;
    const int lane = tid & 31;
    const int g   = lane >> 2;
    const int tir = lane & 3;

    const int aRow = (lane & 7) + ((lane >> 3) & 1) * 8;
    const int aColH = (lane >> 4) * 8;
    const int bRow = (lane & 7) + (lane >> 4) * 8;
    const int bColH = ((lane >> 3) & 1) * 8;

    const uint32_t smb   = smem_u32(fsm);
    const uint32_t qBase = smb + QS_OFF + (((w * 16 + aRow) * QPH + aColH) << 1);
    const uint32_t kBase = smb + KS_OFF + ((bRow * QPH + bColH) << 1);
    const uint32_t vBase = smb + VS_OFF
                         + ((lane & 7) + 8 * ((lane >> 3) & 1)) * VSB
                         + (lane >> 4) * 16;

    const __half* qrow = qkvh + (size_t)(b * TT) * 3 * CC + h * DD;
    const __half* krow = qrow + CC;
    const __half* vrow = qrow + 2 * CC;

    const int jmax = 2 * qb + 1;

    // ---- prefetch K + V block 0 (2 chunks each per thread) ----
#pragma unroll
    for (int t = 0; t < 2; t++) {
        int f = tid + t * 256;
        int row = f >> 3, ch = f & 7;
        cp_async16(fsm + KS_OFF + row * (QPH * 2) + ch * 16,
                   krow + (size_t)row * 3 * CC + ch * 8);
        cp_async16(fsm + VS_OFF + row * VSB + ch * 16,
                   vrow + (size_t)row * 3 * CC + ch * 8);
    }
    CP_COMMIT();

    // ---- stage Q tile (128x64 halfs, already scaled) via cp.async ----
#pragma unroll
    for (int t = 0; t < 4; t++) {
        int f = tid + t * 256;
        int row = f >> 3, ch = f & 7;
        cp_async16(fsm + QS_OFF + row * (QPH * 2) + ch * 16,
                   qrow + (size_t)(qb * 128 + row) * 3 * CC + ch * 8);
    }
    CP_COMMIT();
    CP_WAIT0();
    __syncthreads();

    // ---- hoist Q fragments (loop-invariant): 4 k16-steps ----
    uint32_t aq[4][4];
#pragma unroll
    for (int kk = 0; kk < 4; kk++)
        ldsm4(aq[kk][0], aq[kk][1], aq[kk][2], aq[kk][3],
              qBase + (uint32_t)(kk * 32));

    float m0 = -1e30f, m1 = -1e30f;
    float l0 = 0.f, l1 = 0.f;
    float o[8][4];
#pragma unroll
    for (int nt = 0; nt < 8; nt++)
#pragma unroll
        for (int i = 0; i < 4; i++) o[nt][i] = 0.f;

    for (int j = 0; j <= jmax; j++) {
        if (j == 0) { /* block 0 already resident */ }
        else { CP_WAIT0(); __syncthreads(); }
        if (j + 1 <= jmax) {
            int nb = (j + 1) & 1;
#pragma unroll
            for (int t = 0; t < 2; t++) {
                int f = tid + t * 256;
                int row = f >> 3, ch = f & 7;
                cp_async16(fsm + KS_OFF + nb * KSTG_B + row * (QPH * 2) + ch * 16,
                           krow + (size_t)((j + 1) * 64 + row) * 3 * CC + ch * 8);
                cp_async16(fsm + VS_OFF + nb * VSTG_B + row * VSB + ch * 16,
                           vrow + (size_t)((j + 1) * 64 + row) * 3 * CC + ch * 8);
            }
            CP_COMMIT();
        }
        const uint32_t kStg = (uint32_t)((j & 1) * KSTG_B);
        const uint32_t vStg = (uint32_t)((j & 1) * VSTG_B);

        // ---- S = Qs @ K^T (fp16 k16, exp2 domain): warp computes 16x64 ----
        float s[8][4];
#pragma unroll
        for (int nt = 0; nt < 8; nt++)
#pragma unroll
            for (int i = 0; i < 4; i++) s[nt][i] = 0.f;

#pragma unroll
        for (int kk = 0; kk < 4; kk++) {
            const uint32_t kb = (uint32_t)(kk * 32);
            uint32_t bk[4][4];
#pragma unroll
            for (int ng = 0; ng < 4; ng++)
                ldsm4(bk[ng][0], bk[ng][1], bk[ng][2], bk[ng][3],
                      kBase + kStg + kb + (uint32_t)(ng * 16 * QPH << 1));
#pragma unroll
            for (int ng = 0; ng < 4; ng++) {
                mma16h(s[2*ng  ], aq[kk][0], aq[kk][1], aq[kk][2], aq[kk][3],
                       bk[ng][0], bk[ng][1]);
                mma16h(s[2*ng+1], aq[kk][0], aq[kk][1], aq[kk][2], aq[kk][3],
                       bk[ng][2], bk[ng][3]);
            }
        }

        // ---- causal mask (diagonal-region blocks only) ----
        if (j >= 2 * qb) {
            const int qr0 = qb * 128 + w * 16 + g;
            const int qr1 = qr0 + 8;
            const int jc  = j * 64;
#pragma unroll
            for (int nt = 0; nt < 8; nt++) {
                int c0 = jc + nt * 8 + tir * 2;
                int c1 = c0 + 1;
                if (c0 > qr0) s[nt][0] = -1e30f;
                if (c1 > qr0) s[nt][1] = -1e30f;
                if (c0 > qr1) s[nt][2] = -1e30f;
                if (c1 > qr1) s[nt][3] = -1e30f;
            }
        }

        // ---- online softmax (exp2 domain) ----
        float rm0 = -1e30f, rm1 = -1e30f;
#pragma unroll
        for (int nt = 0; nt < 8; nt++) {
            rm0 = fmaxf(rm0, fmaxf(s[nt][0], s[nt][1]));
            rm1 = fmaxf(rm1, fmaxf(s[nt][2], s[nt][3]));
        }
        rm0 = fmaxf(rm0, __shfl_xor_sync(0xffffffffu, rm0, 1));
        rm0 = fmaxf(rm0, __shfl_xor_sync(0xffffffffu, rm0, 2));
        rm1 = fmaxf(rm1, __shfl_xor_sync(0xffffffffu, rm1, 1));
        rm1 = fmaxf(rm1, __shfl_xor_sync(0xffffffffu, rm1, 2));

        float nm0 = fmaxf(m0, rm0), nm1 = fmaxf(m1, rm1);
        float cf0 = exp2f(m0 - nm0), cf1 = exp2f(m1 - nm1);
        m0 = nm0; m1 = nm1;

        // P in registers as half2 A-fragments (FA2 trick)
        uint32_t phA[8], phB[8];
        float rs0 = 0.f, rs1 = 0.f;
#pragma unroll
        for (int nt = 0; nt < 8; nt++) {
            float p0 = exp2f(s[nt][0] - nm0);
            float p1 = exp2f(s[nt][1] - nm0);
            float p2 = exp2f(s[nt][2] - nm1);
            float p3 = exp2f(s[nt][3] - nm1);
            rs0 += p0 + p1;
            rs1 += p2 + p3;
            phA[nt] = h2(p0, p1);
            phB[nt] = h2(p2, p3);
        }
        rs0 += __shfl_xor_sync(0xffffffffu, rs0, 1);
        rs0 += __shfl_xor_sync(0xffffffffu, rs0, 2);
        rs1 += __shfl_xor_sync(0xffffffffu, rs1, 1);
        rs1 += __shfl_xor_sync(0xffffffffu, rs1, 2);
        l0 = l0 * cf0 + rs0;
        l1 = l1 * cf1 + rs1;

#pragma unroll
        for (int nt = 0; nt < 8; nt++) {
            o[nt][0] *= cf0; o[nt][1] *= cf0;
            o[nt][2] *= cf1; o[nt][3] *= cf1;
        }

        // ---- O += P @ V  (fp16; A regs, B via ldsm4t; R12-validated) ----
#pragma unroll
        for (int kk = 0; kk < 4; kk++) {
            const uint32_t vk = vBase + vStg + (uint32_t)(kk * 16 * VSB);
#pragma unroll
            for (int ng = 0; ng < 4; ng++) {
                uint32_t bv[4];
                ldsm4t(bv[0], bv[1], bv[2], bv[3], vk + (uint32_t)(ng * 32));
                mma16h(o[2*ng  ], phA[2*kk], phB[2*kk],
                       phA[2*kk+1], phB[2*kk+1], bv[0], bv[1]);
                mma16h(o[2*ng+1], phA[2*kk], phB[2*kk],
                       phA[2*kk+1], phB[2*kk+1], bv[2], bv[3]);
            }
        }
        __syncthreads();   // all smem reads done before next stage overwrites
    }

    // ---- normalize, write O as fp16 [B,T,C] (proj GEMM A operand) ----
    const float inv0 = 1.f / l0;
    const float inv1 = 1.f / l1;
    const int t0 = qb * 128 + w * 16 + g;
#pragma unroll
    for (int nt = 0; nt < 8; nt++) {
        int d = nt * 8 + tir * 2;
        *(__half2*)(O + (size_t)(b * TT + t0    ) * CC + h * DD + d) =
            __floats2half2_rn(o[nt][0] * inv0, o[nt][1] * inv0);
        *(__half2*)(O + (size_t)(b * TT + t0 + 8) * CC + h * DD + d) =
            __floats2half2_rn(o[nt][2] * inv1, o[nt][3] * inv1);
    }
}

// ---------------------------------------------------------------------------
// Launch
// ---------------------------------------------------------------------------
extern "C" void kernel_launch(void* const* d_in, const int* in_sizes, int n_in,
                              void* d_out, int out_size)
{
    const float* x      = (const float*)d_in[0];
    const float* w_qkv  = (const float*)d_in[1];
    const float* w_proj = (const float*)d_in[2];
    const float* b_proj = (const float*)d_in[3];
    float* out = (float*)d_out;

    cudaFuncSetAttribute(flash_kernel,
                         cudaFuncAttributeMaxDynamicSharedMemorySize, FLASH_SMEM);

    // 0) x -> fp16; w_qkv -> w_qkv^T fp16 in g_att
    cvt_x_kernel<<<(MTOT * CC / 4) / 256, 256>>>(x);
    transpose_wqkv_kernel<<<dim3(3 * CC / 32, CC / 32), dim3(32, 8)>>>(w_qkv);

    // 1) QKV projection (fp16): Q scaled by 0.125*log2e, all stored fp16
    gemm_qkv_kernel<<<dim3(3 * CC / 128, MTOT / 128), 256, GEMM_SMEM>>>();

    // 2) Fused causal flash attention (all-fp16 MMA): -> g_att fp16
    flash_kernel<<<dim3(TT / 128, BB * HH), 256, FLASH_SMEM>>>();

    // 3) w_proj -> w_proj^T fp16 (x region, dead after QKV GEMM)
    transpose_wproj_kernel<<<dim3(CC / 32, CC / 32), dim3(32, 8)>>>(w_proj);

    // 4) Output projection + bias (fp16 GEMM, fp32 out)
    gemm_proj_kernel<<<dim3(CC / 128, MTOT / 128), 256, GEMM_SMEM>>>(b_proj, out);
}

// round 14
// speedup vs baseline: 2.2462x; 1.0827x over previous
#include <cuda_runtime.h>
#include <cuda_fp16.h>
#include <cstdint>
#include <cstddef>

// Problem constants
#define BB 2
#define TT 2048
#define CC 1024
#define HH 16
#define DD 64
#define MTOT (BB*TT)          // 4096 rows

// 0.125 * log2(e): folded into Q at the QKV epilogue (exp2-domain softmax)
#define QSC 0.1803368801111204f

// ---------------------------------------------------------------------------
// Scratch: exactly 64 MiB (proven footprint), all-fp16 data plan:
//   g_qkv: half view [0:6M floats) = QKV out [4096][3072 halfs] (Q pre-scaled)
//          [6M:8M floats) = x_fp16; dead after QKV GEMM -> w_proj^T fp16
//   g_att: w_qkv^T fp16 before flash; attention out fp16 after flash
// ---------------------------------------------------------------------------
__device__ float g_qkv[(size_t)MTOT * 3 * CC];   // 48 MiB
__device__ float g_att[(size_t)MTOT * CC];       // 16 MiB
#define XH_FOFF  6291456

// ---------------------------------------------------------------------------
// Helpers
// ---------------------------------------------------------------------------
__device__ __forceinline__ void mma16h(float d[4], uint32_t a0, uint32_t a1,
                                       uint32_t a2, uint32_t a3,
                                       uint32_t b0, uint32_t b1) {
    asm volatile(
        "mma.sync.aligned.m16n8k16.row.col.f32.f16.f16.f32 "
        "{%0,%1,%2,%3}, {%4,%5,%6,%7}, {%8,%9}, {%0,%1,%2,%3};\n"
        : "+f"(d[0]), "+f"(d[1]), "+f"(d[2]), "+f"(d[3])
        : "r"(a0), "r"(a1), "r"(a2), "r"(a3), "r"(b0), "r"(b1));
}

__device__ __forceinline__ void ldsm4(uint32_t& r0, uint32_t& r1,
                                      uint32_t& r2, uint32_t& r3, uint32_t addr) {
    asm volatile("ldmatrix.sync.aligned.m8n8.x4.shared.b16 {%0,%1,%2,%3}, [%4];"
                 : "=r"(r0), "=r"(r1), "=r"(r2), "=r"(r3) : "r"(addr));
}
__device__ __forceinline__ void ldsm4t(uint32_t& r0, uint32_t& r1,
                                       uint32_t& r2, uint32_t& r3, uint32_t addr) {
    asm volatile("ldmatrix.sync.aligned.m8n8.x4.trans.shared.b16 {%0,%1,%2,%3}, [%4];"
                 : "=r"(r0), "=r"(r1), "=r"(r2), "=r"(r3) : "r"(addr));
}

__device__ __forceinline__ void cp_async16(void* smem_dst, const void* gsrc) {
    uint32_t s = (uint32_t)__cvta_generic_to_shared(smem_dst);
    asm volatile("cp.async.cg.shared.global [%0], [%1], 16;\n"
                 :: "r"(s), "l"(gsrc) : "memory");
}
#define CP_COMMIT() asm volatile("cp.async.commit_group;\n" ::: "memory")
#define CP_WAIT0()  asm volatile("cp.async.wait_group 0;\n" ::: "memory")

__device__ __forceinline__ uint32_t smem_u32(const void* p) {
    return (uint32_t)__cvta_generic_to_shared(p);
}
__device__ __forceinline__ uint32_t h2(float a, float b) {
    __half2 h = __floats2half2_rn(a, b);
    return *(uint32_t*)&h;
}
__device__ __forceinline__ uint32_t ex2h2(uint32_t d) {
    uint32_t r;
    asm("ex2.approx.f16x2 %0, %1;" : "=r"(r) : "r"(d));
    return r;
}
#define ONE2 0x3C003C00u   // half2(1.0, 1.0)

// ---------------------------------------------------------------------------
// Prep: x -> fp16; W[k][n] -> Wt[n][k] fp16
// ---------------------------------------------------------------------------
__global__ void cvt_x_kernel(const float* __restrict__ x) {
    size_t i = (size_t)blockIdx.x * 256 + threadIdx.x;
    float4 v = ((const float4*)x)[i];
    __half2* dst = (__half2*)(g_qkv + XH_FOFF) + i * 2;
    dst[0] = __floats2half2_rn(v.x, v.y);
    dst[1] = __floats2half2_rn(v.z, v.w);
}

__device__ __forceinline__ void
transpose_cvt_h(const float* __restrict__ W, __half* __restrict__ Wt,
                int K, int N)
{
    __shared__ float tile[32][33];
    int n0 = blockIdx.x * 32, k0 = blockIdx.y * 32;
    int tx = threadIdx.x, ty = threadIdx.y;
#pragma unroll
    for (int i = 0; i < 4; i++)
        tile[ty + 8 * i][tx] = W[(size_t)(k0 + ty + 8 * i) * N + n0 + tx];
    __syncthreads();
#pragma unroll
    for (int i = 0; i < 4; i++)
        Wt[(size_t)(n0 + ty + 8 * i) * K + k0 + tx] =
            __float2half_rn(tile[tx][ty + 8 * i]);
}
__global__ void transpose_wqkv_kernel(const float* __restrict__ w_qkv) {
    transpose_cvt_h(w_qkv, (__half*)g_att, CC, 3 * CC);
}
__global__ void transpose_wproj_kernel(const float* __restrict__ w_proj) {
    transpose_cvt_h(w_proj, (__half*)(g_qkv + XH_FOFF), CC, CC);
}

// ---------------------------------------------------------------------------
// fp16 GEMM: C[M,N] = A[M,K] @ Bt[N,K]^T. 128x128 tile, BK=64 halfs,
// 256 threads (8 warps = 4m x 2n). cp.async 2-stage, ldmatrix, m16n8k16.
// ---------------------------------------------------------------------------
#define GPH 72                     // smem pitch in halfs (144 B): conflict-free
#define GSTGH (128*GPH)            // halfs per operand-stage
#define GEMM_SMEM (4*GSTGH*2)      // 73728 B

__device__ __forceinline__ void
gemm_stage_h(const __half* __restrict__ src, __half* dst, int K, int k0, int tid)
{
#pragma unroll
    for (int t = 0; t < 4; t++) {
        int f = tid + t * 256;
        int row = f >> 3, ch = f & 7;
        cp_async16(dst + row * GPH + ch * 8, src + (size_t)row * K + k0 + ch * 8);
    }
}

// Shared mainloop producing acc[2][8][4] for a 128x128 tile
#define GEMM_PROLOG_AND_LOOP(A_, Bt_, K_)                                      \
    const int tid  = threadIdx.x;                                              \
    const int bm   = blockIdx.y;                                               \
    const int bn   = blockIdx.x;                                               \
    const int warp = tid >> 5;                                                 \
    const int lane = tid & 31;                                                 \
    const int wm   = warp & 3;                                                 \
    const int wn   = warp >> 2;                                                \
    const int g    = lane >> 2;                                                \
    const int tir  = lane & 3;                                                 \
    const int aRow = (lane & 7) + ((lane >> 3) & 1) * 8;                       \
    const int aColH = (lane >> 4) * 8;                                         \
    const int bRow = (lane & 7) + (lane >> 4) * 8;                             \
    const int bColH = ((lane >> 3) & 1) * 8;                                   \
    const uint32_t aBase = smem_u32(As) + (((wm * 32 + aRow) * GPH + aColH) << 1); \
    const uint32_t bBase = smem_u32(Bs) + (((wn * 64 + bRow) * GPH + bColH) << 1); \
    float acc[2][8][4];                                                        \
    _Pragma("unroll")                                                          \
    for (int mt = 0; mt < 2; mt++)                                             \
        _Pragma("unroll")                                                      \
        for (int nt = 0; nt < 8; nt++)                                         \
            _Pragma("unroll")                                                  \
            for (int i = 0; i < 4; i++) acc[mt][nt][i] = 0.0f;                 \
    const __half* Ablk = (A_)  + (size_t)(bm * 128) * (K_);                    \
    const __half* Bblk = (Bt_) + (size_t)(bn * 128) * (K_);                    \
    const int NT = (K_) >> 6;                                                  \
    gemm_stage_h(Ablk, As, (K_), 0, tid);                                      \
    gemm_stage_h(Bblk, Bs, (K_), 0, tid);                                      \
    CP_COMMIT();                                                               \
    for (int it = 0; it < NT; it++) {                                          \
        CP_WAIT0();                                                            \
        __syncthreads();                                                       \
        if (it + 1 < NT) {                                                     \
            int nb = (it + 1) & 1;                                             \
            gemm_stage_h(Ablk, As + nb * GSTGH, (K_), (it + 1) * 64, tid);     \
            gemm_stage_h(Bblk, Bs + nb * GSTGH, (K_), (it + 1) * 64, tid);     \
            CP_COMMIT();                                                       \
        }                                                                      \
        const uint32_t stg = (uint32_t)((it & 1) * GSTGH * 2);                 \
        _Pragma("unroll")                                                      \
        for (int kk = 0; kk < 4; kk++) {                                       \
            const uint32_t kb = (uint32_t)(kk * 32);                           \
            uint32_t a[2][4];                                                  \
            ldsm4(a[0][0], a[0][1], a[0][2], a[0][3], aBase + stg + kb);       \
            ldsm4(a[1][0], a[1][1], a[1][2], a[1][3],                          \
                  aBase + stg + kb + (16 * GPH << 1));                         \
            uint32_t b[4][4];                                                  \
            _Pragma("unroll")                                                  \
            for (int ng = 0; ng < 4; ng++)                                     \
                ldsm4(b[ng][0], b[ng][1], b[ng][2], b[ng][3],                  \
                      bBase + stg + kb + (uint32_t)(ng * 16 * GPH << 1));      \
            _Pragma("unroll")                                                  \
            for (int ng = 0; ng < 4; ng++) {                                   \
                mma16h(acc[0][2*ng  ], a[0][0], a[0][1], a[0][2], a[0][3],     \
                       b[ng][0], b[ng][1]);                                    \
                mma16h(acc[0][2*ng+1], a[0][0], a[0][1], a[0][2], a[0][3],     \
                       b[ng][2], b[ng][3]);                                    \
                mma16h(acc[1][2*ng  ], a[1][0], a[1][1], a[1][2], a[1][3],     \
                       b[ng][0], b[ng][1]);                                    \
                mma16h(acc[1][2*ng+1], a[1][0], a[1][1], a[1][2], a[1][3],     \
                       b[ng][2], b[ng][3]);                                    \
            }                                                                  \
        }                                                                      \
        __syncthreads();                                                       \
    }

// QKV: A = x_fp16, B = w_qkv^T; out fp16 (Q cols scaled by QSC)
__global__ void __launch_bounds__(256, 2)
gemm_qkv_kernel()
{
    extern __shared__ char smc[];
    __half* As = (__half*)smc;
    __half* Bs = As + 2 * GSTGH;
    GEMM_PROLOG_AND_LOOP((const __half*)(g_qkv + XH_FOFF),
                         (const __half*)g_att, CC)

    __half* Ch = (__half*)g_qkv;
#pragma unroll
    for (int mt = 0; mt < 2; mt++) {
#pragma unroll
        for (int nt = 0; nt < 8; nt++) {
            int row = bm * 128 + wm * 32 + mt * 16 + g;
            int col = bn * 128 + wn * 64 + nt * 8 + tir * 2;
            float v00 = acc[mt][nt][0], v01 = acc[mt][nt][1];
            float v10 = acc[mt][nt][2], v11 = acc[mt][nt][3];
            if (col < CC) { v00 *= QSC; v01 *= QSC; v10 *= QSC; v11 *= QSC; }
            *(__half2*)(Ch + (size_t)row * (3 * CC) + col) =
                __floats2half2_rn(v00, v01);
            *(__half2*)(Ch + (size_t)(row + 8) * (3 * CC) + col) =
                __floats2half2_rn(v10, v11);
        }
    }
}

// Proj: A = attention out fp16, B = w_proj^T; out fp32 + bias
__global__ void __launch_bounds__(256, 2)
gemm_proj_kernel(const float* __restrict__ b_proj, float* __restrict__ out)
{
    extern __shared__ char smc[];
    __half* As = (__half*)smc;
    __half* Bs = As + 2 * GSTGH;
    GEMM_PROLOG_AND_LOOP((const __half*)g_att,
                         (const __half*)(g_qkv + XH_FOFF), CC)

#pragma unroll
    for (int mt = 0; mt < 2; mt++) {
#pragma unroll
        for (int nt = 0; nt < 8; nt++) {
            int row = bm * 128 + wm * 32 + mt * 16 + g;
            int col = bn * 128 + wn * 64 + nt * 8 + tir * 2;
            float bb0 = b_proj[col], bb1 = b_proj[col + 1];
            *(float2*)(out + (size_t)row * CC + col) =
                make_float2(acc[mt][nt][0] + bb0, acc[mt][nt][1] + bb1);
            *(float2*)(out + (size_t)(row + 8) * CC + col) =
                make_float2(acc[mt][nt][2] + bb0, acc[mt][nt][3] + bb1);
        }
    }
}

// ---------------------------------------------------------------------------
// Flash attention (causal), all-fp16 MMA, exp2-domain softmax.
// NEW vs R13: P computed via ex2.approx.f16x2 (half the MUFU ops; d = s-m in
// fp32 first), and row-sum l accumulated via ones-column MMA (no shuffles).
// smem 55296 B -> 2 CTAs/SM. grid=(T/128, B*H), 8 warps.
// ---------------------------------------------------------------------------
#define QPH 72                             // Q/K smem pitch in halfs (144 B)
#define VSB 144                            // V smem row pitch (bytes)
#define QS_OFF 0
#define KS_OFF (128*QPH*2)                 // 18432
#define KSTG_B (64*QPH*2)                  // 9216
#define VS_OFF (KS_OFF + 2*KSTG_B)         // 36864
#define VSTG_B (64*VSB)                    // 9216
#define FLASH_SMEM (VS_OFF + 2*VSTG_B)     // 55296

__global__ void __launch_bounds__(256, 2)
flash_kernel()
{
    extern __shared__ char fsm[];

    const __half* qkvh = (const __half*)g_qkv;
    __half* O = (__half*)g_att;

    const int qb  = (gridDim.x - 1) - blockIdx.x;   // heavy blocks first
    const int bh  = blockIdx.y;
    const int b   = bh >> 4;
    const int h   = bh & 15;
    const int tid = threadIdx.x;
    const int w   = tid >> 5;
    const int lane = tid & 31;
    const int g   = lane >> 2;
    const int tir = lane & 3;

    const int aRow = (lane & 7) + ((lane >> 3) & 1) * 8;
    const int aColH = (lane >> 4) * 8;
    const int bRow = (lane & 7) + (lane >> 4) * 8;
    const int bColH = ((lane >> 3) & 1) * 8;

    const uint32_t smb   = smem_u32(fsm);
    const uint32_t qBase = smb + QS_OFF + (((w * 16 + aRow) * QPH + aColH) << 1);
    const uint32_t kBase = smb + KS_OFF + ((bRow * QPH + bColH) << 1);
    const uint32_t vBase = smb + VS_OFF
                         + ((lane & 7) + 8 * ((lane >> 3) & 1)) * VSB
                         + (lane >> 4) * 16;

    const __half* qrow = qkvh + (size_t)(b * TT) * 3 * CC + h * DD;
    const __half* krow = qrow + CC;
    const __half* vrow = qrow + 2 * CC;

    const int jmax = 2 * qb + 1;

    // ---- prefetch K + V block 0 ----
#pragma unroll
    for (int t = 0; t < 2; t++) {
        int f = tid + t * 256;
        int row = f >> 3, ch = f & 7;
        cp_async16(fsm + KS_OFF + row * (QPH * 2) + ch * 16,
                   krow + (size_t)row * 3 * CC + ch * 8);
        cp_async16(fsm + VS_OFF + row * VSB + ch * 16,
                   vrow + (size_t)row * 3 * CC + ch * 8);
    }
    CP_COMMIT();

    // ---- stage Q tile (pre-scaled fp16) ----
#pragma unroll
    for (int t = 0; t < 4; t++) {
        int f = tid + t * 256;
        int row = f >> 3, ch = f & 7;
        cp_async16(fsm + QS_OFF + row * (QPH * 2) + ch * 16,
                   qrow + (size_t)(qb * 128 + row) * 3 * CC + ch * 8);
    }
    CP_COMMIT();
    CP_WAIT0();
    __syncthreads();

    // ---- hoist Q fragments (loop-invariant): 4 k16-steps ----
    uint32_t aq[4][4];
#pragma unroll
    for (int kk = 0; kk < 4; kk++)
        ldsm4(aq[kk][0], aq[kk][1], aq[kk][2], aq[kk][3],
              qBase + (uint32_t)(kk * 32));

    float m0 = -1e30f, m1 = -1e30f;
    float ol[4] = {0.f, 0.f, 0.f, 0.f};   // row-sum accumulator (ones column)
    float o[8][4];
#pragma unroll
    for (int nt = 0; nt < 8; nt++)
#pragma unroll
        for (int i = 0; i < 4; i++) o[nt][i] = 0.f;

    for (int j = 0; j <= jmax; j++) {
        if (j > 0) { CP_WAIT0(); __syncthreads(); }
        if (j + 1 <= jmax) {
            int nb = (j + 1) & 1;
#pragma unroll
            for (int t = 0; t < 2; t++) {
                int f = tid + t * 256;
                int row = f >> 3, ch = f & 7;
                cp_async16(fsm + KS_OFF + nb * KSTG_B + row * (QPH * 2) + ch * 16,
                           krow + (size_t)((j + 1) * 64 + row) * 3 * CC + ch * 8);
                cp_async16(fsm + VS_OFF + nb * VSTG_B + row * VSB + ch * 16,
                           vrow + (size_t)((j + 1) * 64 + row) * 3 * CC + ch * 8);
            }
            CP_COMMIT();
        }
        const uint32_t kStg = (uint32_t)((j & 1) * KSTG_B);
        const uint32_t vStg = (uint32_t)((j & 1) * VSTG_B);

        // ---- S = Qs @ K^T (fp16 k16, exp2 domain): warp computes 16x64 ----
        float s[8][4];
#pragma unroll
        for (int nt = 0; nt < 8; nt++)
#pragma unroll
            for (int i = 0; i < 4; i++) s[nt][i] = 0.f;

#pragma unroll
        for (int kk = 0; kk < 4; kk++) {
            const uint32_t kb = (uint32_t)(kk * 32);
            uint32_t bk[4][4];
#pragma unroll
            for (int ng = 0; ng < 4; ng++)
                ldsm4(bk[ng][0], bk[ng][1], bk[ng][2], bk[ng][3],
                      kBase + kStg + kb + (uint32_t)(ng * 16 * QPH << 1));
#pragma unroll
            for (int ng = 0; ng < 4; ng++) {
                mma16h(s[2*ng  ], aq[kk][0], aq[kk][1], aq[kk][2], aq[kk][3],
                       bk[ng][0], bk[ng][1]);
                mma16h(s[2*ng+1], aq[kk][0], aq[kk][1], aq[kk][2], aq[kk][3],
                       bk[ng][2], bk[ng][3]);
            }
        }

        // ---- causal mask (diagonal-region blocks only) ----
        if (j >= 2 * qb) {
            const int qr0 = qb * 128 + w * 16 + g;
            const int qr1 = qr0 + 8;
            const int jc  = j * 64;
#pragma unroll
            for (int nt = 0; nt < 8; nt++) {
                int c0 = jc + nt * 8 + tir * 2;
                int c1 = c0 + 1;
                if (c0 > qr0) s[nt][0] = -1e30f;
                if (c1 > qr0) s[nt][1] = -1e30f;
                if (c0 > qr1) s[nt][2] = -1e30f;
                if (c1 > qr1) s[nt][3] = -1e30f;
            }
        }

        // ---- online softmax (exp2 domain) ----
        float rm0 = -1e30f, rm1 = -1e30f;
#pragma unroll
        for (int nt = 0; nt < 8; nt++) {
            rm0 = fmaxf(rm0, fmaxf(s[nt][0], s[nt][1]));
            rm1 = fmaxf(rm1, fmaxf(s[nt][2], s[nt][3]));
        }
        rm0 = fmaxf(rm0, __shfl_xor_sync(0xffffffffu, rm0, 1));
        rm0 = fmaxf(rm0, __shfl_xor_sync(0xffffffffu, rm0, 2));
        rm1 = fmaxf(rm1, __shfl_xor_sync(0xffffffffu, rm1, 1));
        rm1 = fmaxf(rm1, __shfl_xor_sync(0xffffffffu, rm1, 2));

        float nm0 = fmaxf(m0, rm0), nm1 = fmaxf(m1, rm1);
        float cf0 = exp2f(m0 - nm0), cf1 = exp2f(m1 - nm1);
        m0 = nm0; m1 = nm1;

        // P via ex2.approx.f16x2: d computed in fp32, rounded to fp16, exp'd
        uint32_t phA[8], phB[8];
#pragma unroll
        for (int nt = 0; nt < 8; nt++) {
            phA[nt] = ex2h2(h2(s[nt][0] - nm0, s[nt][1] - nm0));
            phB[nt] = ex2h2(h2(s[nt][2] - nm1, s[nt][3] - nm1));
        }

        // rescale running accumulators (o and row-sum ol)
#pragma unroll
        for (int nt = 0; nt < 8; nt++) {
            o[nt][0] *= cf0; o[nt][1] *= cf0;
            o[nt][2] *= cf1; o[nt][3] *= cf1;
        }
        ol[0] *= cf0; ol[1] *= cf0; ol[2] *= cf1; ol[3] *= cf1;

        // ---- O += P @ V ; ol += P @ ones (row sums, no shuffles) ----
#pragma unroll
        for (int kk = 0; kk < 4; kk++) {
            const uint32_t vk = vBase + vStg + (uint32_t)(kk * 16 * VSB);
#pragma unroll
            for (int ng = 0; ng < 4; ng++) {
                uint32_t bv[4];
                ldsm4t(bv[0], bv[1], bv[2], bv[3], vk + (uint32_t)(ng * 32));
                mma16h(o[2*ng  ], phA[2*kk], phB[2*kk],
                       phA[2*kk+1], phB[2*kk+1], bv[0], bv[1]);
                mma16h(o[2*ng+1], phA[2*kk], phB[2*kk],
                       phA[2*kk+1], phB[2*kk+1], bv[2], bv[3]);
            }
            mma16h(ol, phA[2*kk], phB[2*kk], phA[2*kk+1], phB[2*kk+1],
                   ONE2, ONE2);
        }
        __syncthreads();   // all smem reads done before next stage overwrites
    }

    // ---- normalize (l = ol, no reduction needed), write O fp16 [B,T,C] ----
    const float inv0 = 1.f / ol[0];
    const float inv1 = 1.f / ol[2];
    const int t0 = qb * 128 + w * 16 + g;
#pragma unroll
    for (int nt = 0; nt < 8; nt++) {
        int d = nt * 8 + tir * 2;
        *(__half2*)(O + (size_t)(b * TT + t0    ) * CC + h * DD + d) =
            __floats2half2_rn(o[nt][0] * inv0, o[nt][1] * inv0);
        *(__half2*)(O + (size_t)(b * TT + t0 + 8) * CC + h * DD + d) =
            __floats2half2_rn(o[nt][2] * inv1, o[nt][3] * inv1);
    }
}

// ---------------------------------------------------------------------------
// Launch
// ---------------------------------------------------------------------------
extern "C" void kernel_launch(void* const* d_in, const int* in_sizes, int n_in,
                              void* d_out, int out_size)
{
    const float* x      = (const float*)d_in[0];
    const float* w_qkv  = (const float*)d_in[1];
    const float* w_proj = (const float*)d_in[2];
    const float* b_proj = (const float*)d_in[3];
    float* out = (float*)d_out;

    cudaFuncSetAttribute(gemm_qkv_kernel,
                         cudaFuncAttributeMaxDynamicSharedMemorySize, GEMM_SMEM);
    cudaFuncSetAttribute(gemm_proj_kernel,
                         cudaFuncAttributeMaxDynamicSharedMemorySize, GEMM_SMEM);
    cudaFuncSetAttribute(flash_kernel,
                         cudaFuncAttributeMaxDynamicSharedMemorySize, FLASH_SMEM);

    // 0) x -> fp16; w_qkv -> w_qkv^T fp16 in g_att
    cvt_x_kernel<<<(MTOT * CC / 4) / 256, 256>>>(x);
    transpose_wqkv_kernel<<<dim3(3 * CC / 32, CC / 32), dim3(32, 8)>>>(w_qkv);

    // 1) QKV projection (fp16, BK=64): Q scaled by 0.125*log2e
    gemm_qkv_kernel<<<dim3(3 * CC / 128, MTOT / 128), 256, GEMM_SMEM>>>();

    // 2) Fused causal flash attention: -> g_att fp16
    flash_kernel<<<dim3(TT / 128, BB * HH), 256, FLASH_SMEM>>>();

    // 3) w_proj -> w_proj^T fp16 (x region, dead after QKV GEMM)
    transpose_wproj_kernel<<<dim3(CC / 32, CC / 32), dim3(32, 8)>>>(w_proj);

    // 4) Output projection + bias (fp16 GEMM, fp32 out)
    gemm_proj_kernel<<<dim3(CC / 128, MTOT / 128), 256, GEMM_SMEM>>>(b_proj, out);
}

// round 15
// speedup vs baseline: 2.4458x; 1.0889x over previous
#include <cuda_runtime.h>
#include <cuda_fp16.h>
#include <cstdint>
#include <cstddef>

// Problem constants
#define BB 2
#define TT 2048
#define CC 1024
#define HH 16
#define DD 64
#define MTOT (BB*TT)          // 4096 rows
#define NQB (TT/128)          // 16 q-blocks per (b,h)

// 0.125 * log2(e): folded into Q at the QKV epilogue (exp2-domain softmax)
#define QSC 0.1803368801111204f

// ---------------------------------------------------------------------------
// Scratch: exactly 64 MiB (proven footprint), all-fp16 data plan:
//   g_qkv: half view [0:6M floats) = QKV out [4096][3072 halfs] (Q pre-scaled)
//          [6M:8M floats) = x_fp16; dead after QKV GEMM -> w_proj^T fp16
//   g_att: w_qkv^T fp16 before flash; attention out fp16 after flash
// ---------------------------------------------------------------------------
__device__ float g_qkv[(size_t)MTOT * 3 * CC];   // 48 MiB
__device__ float g_att[(size_t)MTOT * CC];       // 16 MiB
#define XH_FOFF  6291456

// ---------------------------------------------------------------------------
// Helpers
// ---------------------------------------------------------------------------
__device__ __forceinline__ void mma16h(float d[4], uint32_t a0, uint32_t a1,
                                       uint32_t a2, uint32_t a3,
                                       uint32_t b0, uint32_t b1) {
    asm volatile(
        "mma.sync.aligned.m16n8k16.row.col.f32.f16.f16.f32 "
        "{%0,%1,%2,%3}, {%4,%5,%6,%7}, {%8,%9}, {%0,%1,%2,%3};\n"
        : "+f"(d[0]), "+f"(d[1]), "+f"(d[2]), "+f"(d[3])
        : "r"(a0), "r"(a1), "r"(a2), "r"(a3), "r"(b0), "r"(b1));
}

__device__ __forceinline__ void ldsm4(uint32_t& r0, uint32_t& r1,
                                      uint32_t& r2, uint32_t& r3, uint32_t addr) {
    asm volatile("ldmatrix.sync.aligned.m8n8.x4.shared.b16 {%0,%1,%2,%3}, [%4];"
                 : "=r"(r0), "=r"(r1), "=r"(r2), "=r"(r3) : "r"(addr));
}
__device__ __forceinline__ void ldsm4t(uint32_t& r0, uint32_t& r1,
                                       uint32_t& r2, uint32_t& r3, uint32_t addr) {
    asm volatile("ldmatrix.sync.aligned.m8n8.x4.trans.shared.b16 {%0,%1,%2,%3}, [%4];"
                 : "=r"(r0), "=r"(r1), "=r"(r2), "=r"(r3) : "r"(addr));
}

__device__ __forceinline__ void cp_async16(void* smem_dst, const void* gsrc) {
    uint32_t s = (uint32_t)__cvta_generic_to_shared(smem_dst);
    asm volatile("cp.async.cg.shared.global [%0], [%1], 16;\n"
                 :: "r"(s), "l"(gsrc) : "memory");
}
#define CP_COMMIT() asm volatile("cp.async.commit_group;\n" ::: "memory")
#define CP_WAIT0()  asm volatile("cp.async.wait_group 0;\n" ::: "memory")

__device__ __forceinline__ uint32_t smem_u32(const void* p) {
    return (uint32_t)__cvta_generic_to_shared(p);
}
__device__ __forceinline__ uint32_t h2(float a, float b) {
    __half2 h = __floats2half2_rn(a, b);
    return *(uint32_t*)&h;
}
__device__ __forceinline__ uint32_t ex2h2(uint32_t d) {
    uint32_t r;
    asm("ex2.approx.f16x2 %0, %1;" : "=r"(r) : "r"(d));
    return r;
}
#define ONE2 0x3C003C00u   // half2(1.0, 1.0)

// ---------------------------------------------------------------------------
// Prep: x -> fp16; W[k][n] -> Wt[n][k] fp16
// ---------------------------------------------------------------------------
__global__ void cvt_x_kernel(const float* __restrict__ x) {
    size_t i = (size_t)blockIdx.x * 256 + threadIdx.x;
    float4 v = ((const float4*)x)[i];
    __half2* dst = (__half2*)(g_qkv + XH_FOFF) + i * 2;
    dst[0] = __floats2half2_rn(v.x, v.y);
    dst[1] = __floats2half2_rn(v.z, v.w);
}

__device__ __forceinline__ void
transpose_cvt_h(const float* __restrict__ W, __half* __restrict__ Wt,
                int K, int N)
{
    __shared__ float tile[32][33];
    int n0 = blockIdx.x * 32, k0 = blockIdx.y * 32;
    int tx = threadIdx.x, ty = threadIdx.y;
#pragma unroll
    for (int i = 0; i < 4; i++)
        tile[ty + 8 * i][tx] = W[(size_t)(k0 + ty + 8 * i) * N + n0 + tx];
    __syncthreads();
#pragma unroll
    for (int i = 0; i < 4; i++)
        Wt[(size_t)(n0 + ty + 8 * i) * K + k0 + tx] =
            __float2half_rn(tile[tx][ty + 8 * i]);
}
__global__ void transpose_wqkv_kernel(const float* __restrict__ w_qkv) {
    transpose_cvt_h(w_qkv, (__half*)g_att, CC, 3 * CC);
}
__global__ void transpose_wproj_kernel(const float* __restrict__ w_proj) {
    transpose_cvt_h(w_proj, (__half*)(g_qkv + XH_FOFF), CC, CC);
}

// ---------------------------------------------------------------------------
// fp16 GEMM: C[M,N] = A[M,K] @ Bt[N,K]^T. 128x128 tile, BK=64 halfs,
// 256 threads (8 warps = 4m x 2n). cp.async 2-stage, ldmatrix, m16n8k16.
// ---------------------------------------------------------------------------
#define GPH 72                     // smem pitch in halfs (144 B): conflict-free
#define GSTGH (128*GPH)            // halfs per operand-stage
#define GEMM_SMEM (4*GSTGH*2)      // 73728 B

__device__ __forceinline__ void
gemm_stage_h(const __half* __restrict__ src, __half* dst, int K, int k0, int tid)
{
#pragma unroll
    for (int t = 0; t < 4; t++) {
        int f = tid + t * 256;
        int row = f >> 3, ch = f & 7;
        cp_async16(dst + row * GPH + ch * 8, src + (size_t)row * K + k0 + ch * 8);
    }
}

// Shared mainloop producing acc[2][8][4] for a 128x128 tile
#define GEMM_PROLOG_AND_LOOP(A_, Bt_, K_)                                      \
    const int tid  = threadIdx.x;                                              \
    const int bm   = blockIdx.y;                                               \
    const int bn   = blockIdx.x;                                               \
    const int warp = tid >> 5;                                                 \
    const int lane = tid & 31;                                                 \
    const int wm   = warp & 3;                                                 \
    const int wn   = warp >> 2;                                                \
    const int g    = lane >> 2;                                                \
    const int tir  = lane & 3;                                                 \
    const int aRow = (lane & 7) + ((lane >> 3) & 1) * 8;                       \
    const int aColH = (lane >> 4) * 8;                                         \
    const int bRow = (lane & 7) + (lane >> 4) * 8;                             \
    const int bColH = ((lane >> 3) & 1) * 8;                                   \
    const uint32_t aBase = smem_u32(As) + (((wm * 32 + aRow) * GPH + aColH) << 1); \
    const uint32_t bBase = smem_u32(Bs) + (((wn * 64 + bRow) * GPH + bColH) << 1); \
    float acc[2][8][4];                                                        \
    _Pragma("unroll")                                                          \
    for (int mt = 0; mt < 2; mt++)                                             \
        _Pragma("unroll")                                                      \
        for (int nt = 0; nt < 8; nt++)                                         \
            _Pragma("unroll")                                                  \
            for (int i = 0; i < 4; i++) acc[mt][nt][i] = 0.0f;                 \
    const __half* Ablk = (A_)  + (size_t)(bm * 128) * (K_);                    \
    const __half* Bblk = (Bt_) + (size_t)(bn * 128) * (K_);                    \
    const int NT = (K_) >> 6;                                                  \
    gemm_stage_h(Ablk, As, (K_), 0, tid);                                      \
    gemm_stage_h(Bblk, Bs, (K_), 0, tid);                                      \
    CP_COMMIT();                                                               \
    for (int it = 0; it < NT; it++) {                                          \
        CP_WAIT0();                                                            \
        __syncthreads();                                                       \
        if (it + 1 < NT) {                                                     \
            int nb = (it + 1) & 1;                                             \
            gemm_stage_h(Ablk, As + nb * GSTGH, (K_), (it + 1) * 64, tid);     \
            gemm_stage_h(Bblk, Bs + nb * GSTGH, (K_), (it + 1) * 64, tid);     \
            CP_COMMIT();                                                       \
        }                                                                      \
        const uint32_t stg = (uint32_t)((it & 1) * GSTGH * 2);                 \
        _Pragma("unroll")                                                      \
        for (int kk = 0; kk < 4; kk++) {                                       \
            const uint32_t kb = (uint32_t)(kk * 32);                           \
            uint32_t a[2][4];                                                  \
            ldsm4(a[0][0], a[0][1], a[0][2], a[0][3], aBase + stg + kb);       \
            ldsm4(a[1][0], a[1][1], a[1][2], a[1][3],                          \
                  aBase + stg + kb + (16 * GPH << 1));                         \
            uint32_t b[4][4];                                                  \
            _Pragma("unroll")                                                  \
            for (int ng = 0; ng < 4; ng++)                                     \
                ldsm4(b[ng][0], b[ng][1], b[ng][2], b[ng][3],                  \
                      bBase + stg + kb + (uint32_t)(ng * 16 * GPH << 1));      \
            _Pragma("unroll")                                                  \
            for (int ng = 0; ng < 4; ng++) {                                   \
                mma16h(acc[0][2*ng  ], a[0][0], a[0][1], a[0][2], a[0][3],     \
                       b[ng][0], b[ng][1]);                                    \
                mma16h(acc[0][2*ng+1], a[0][0], a[0][1], a[0][2], a[0][3],     \
                       b[ng][2], b[ng][3]);                                    \
                mma16h(acc[1][2*ng  ], a[1][0], a[1][1], a[1][2], a[1][3],     \
                       b[ng][0], b[ng][1]);                                    \
                mma16h(acc[1][2*ng+1], a[1][0], a[1][1], a[1][2], a[1][3],     \
                       b[ng][2], b[ng][3]);                                    \
            }                                                                  \
        }                                                                      \
        __syncthreads();                                                       \
    }

// QKV: A = x_fp16, B = w_qkv^T; out fp16 (Q cols scaled by QSC)
__global__ void __launch_bounds__(256, 2)
gemm_qkv_kernel()
{
    extern __shared__ char smc[];
    __half* As = (__half*)smc;
    __half* Bs = As + 2 * GSTGH;
    GEMM_PROLOG_AND_LOOP((const __half*)(g_qkv + XH_FOFF),
                         (const __half*)g_att, CC)

    __half* Ch = (__half*)g_qkv;
#pragma unroll
    for (int mt = 0; mt < 2; mt++) {
#pragma unroll
        for (int nt = 0; nt < 8; nt++) {
            int row = bm * 128 + wm * 32 + mt * 16 + g;
            int col = bn * 128 + wn * 64 + nt * 8 + tir * 2;
            float v00 = acc[mt][nt][0], v01 = acc[mt][nt][1];
            float v10 = acc[mt][nt][2], v11 = acc[mt][nt][3];
            if (col < CC) { v00 *= QSC; v01 *= QSC; v10 *= QSC; v11 *= QSC; }
            *(__half2*)(Ch + (size_t)row * (3 * CC) + col) =
                __floats2half2_rn(v00, v01);
            *(__half2*)(Ch + (size_t)(row + 8) * (3 * CC) + col) =
                __floats2half2_rn(v10, v11);
        }
    }
}

// Proj: A = attention out fp16, B = w_proj^T; out fp32 + bias
__global__ void __launch_bounds__(256, 2)
gemm_proj_kernel(const float* __restrict__ b_proj, float* __restrict__ out)
{
    extern __shared__ char smc[];
    __half* As = (__half*)smc;
    __half* Bs = As + 2 * GSTGH;
    GEMM_PROLOG_AND_LOOP((const __half*)g_att,
                         (const __half*)(g_qkv + XH_FOFF), CC)

#pragma unroll
    for (int mt = 0; mt < 2; mt++) {
#pragma unroll
        for (int nt = 0; nt < 8; nt++) {
            int row = bm * 128 + wm * 32 + mt * 16 + g;
            int col = bn * 128 + wn * 64 + nt * 8 + tir * 2;
            float bb0 = b_proj[col], bb1 = b_proj[col + 1];
            *(float2*)(out + (size_t)row * CC + col) =
                make_float2(acc[mt][nt][0] + bb0, acc[mt][nt][1] + bb1);
            *(float2*)(out + (size_t)(row + 8) * CC + col) =
                make_float2(acc[mt][nt][2] + bb0, acc[mt][nt][3] + bb1);
        }
    }
}

// ---------------------------------------------------------------------------
// Flash attention (causal), all-fp16 MMA, exp2-domain softmax.
// NEW vs R14: causal work balancing — each CTA processes the q-block PAIR
// {p, NQB-1-p}, so every CTA does exactly 34 block-iters (was 2..32 spread
// over 512 CTAs). grid = (NQB/2, B*H) = 256 CTAs -> one uniform wave.
// smem 55296 B -> 2 CTAs/SM. 8 warps.
// ---------------------------------------------------------------------------
#define QPH 72                             // Q/K smem pitch in halfs (144 B)
#define VSB 144                            // V smem row pitch (bytes)
#define QS_OFF 0
#define KS_OFF (128*QPH*2)                 // 18432
#define KSTG_B (64*QPH*2)                  // 9216
#define VS_OFF (KS_OFF + 2*KSTG_B)         // 36864
#define VSTG_B (64*VSB)                    // 9216
#define FLASH_SMEM (VS_OFF + 2*VSTG_B)     // 55296

__device__ __forceinline__ void
flash_tile(char* fsm, const __half* qrow, const __half* krow,
           const __half* vrow, __half* O, int b, int h, int qb,
           int tid, int w, int lane, int g, int tir,
           uint32_t qBase, uint32_t kBase, uint32_t vBase)
{
    const int jmax = 2 * qb + 1;

    // ---- prefetch K + V block 0 ----
#pragma unroll
    for (int t = 0; t < 2; t++) {
        int f = tid + t * 256;
        int row = f >> 3, ch = f & 7;
        cp_async16(fsm + KS_OFF + row * (QPH * 2) + ch * 16,
                   krow + (size_t)row * 3 * CC + ch * 8);
        cp_async16(fsm + VS_OFF + row * VSB + ch * 16,
                   vrow + (size_t)row * 3 * CC + ch * 8);
    }
    CP_COMMIT();

    // ---- stage Q tile (pre-scaled fp16) ----
#pragma unroll
    for (int t = 0; t < 4; t++) {
        int f = tid + t * 256;
        int row = f >> 3, ch = f & 7;
        cp_async16(fsm + QS_OFF + row * (QPH * 2) + ch * 16,
                   qrow + (size_t)(qb * 128 + row) * 3 * CC + ch * 8);
    }
    CP_COMMIT();
    CP_WAIT0();
    __syncthreads();

    // ---- hoist Q fragments (loop-invariant): 4 k16-steps ----
    uint32_t aq[4][4];
#pragma unroll
    for (int kk = 0; kk < 4; kk++)
        ldsm4(aq[kk][0], aq[kk][1], aq[kk][2], aq[kk][3],
              qBase + (uint32_t)(kk * 32));

    float m0 = -1e30f, m1 = -1e30f;
    float ol[4] = {0.f, 0.f, 0.f, 0.f};
    float o[8][4];
#pragma unroll
    for (int nt = 0; nt < 8; nt++)
#pragma unroll
        for (int i = 0; i < 4; i++) o[nt][i] = 0.f;

    for (int j = 0; j <= jmax; j++) {
        if (j > 0) { CP_WAIT0(); __syncthreads(); }
        if (j + 1 <= jmax) {
            int nb = (j + 1) & 1;
#pragma unroll
            for (int t = 0; t < 2; t++) {
                int f = tid + t * 256;
                int row = f >> 3, ch = f & 7;
                cp_async16(fsm + KS_OFF + nb * KSTG_B + row * (QPH * 2) + ch * 16,
                           krow + (size_t)((j + 1) * 64 + row) * 3 * CC + ch * 8);
                cp_async16(fsm + VS_OFF + nb * VSTG_B + row * VSB + ch * 16,
                           vrow + (size_t)((j + 1) * 64 + row) * 3 * CC + ch * 8);
            }
            CP_COMMIT();
        }
        const uint32_t kStg = (uint32_t)((j & 1) * KSTG_B);
        const uint32_t vStg = (uint32_t)((j & 1) * VSTG_B);

        // ---- S = Qs @ K^T (fp16 k16, exp2 domain): warp computes 16x64 ----
        float s[8][4];
#pragma unroll
        for (int nt = 0; nt < 8; nt++)
#pragma unroll
            for (int i = 0; i < 4; i++) s[nt][i] = 0.f;

#pragma unroll
        for (int kk = 0; kk < 4; kk++) {
            const uint32_t kb = (uint32_t)(kk * 32);
            uint32_t bk[4][4];
#pragma unroll
            for (int ng = 0; ng < 4; ng++)
                ldsm4(bk[ng][0], bk[ng][1], bk[ng][2], bk[ng][3],
                      kBase + kStg + kb + (uint32_t)(ng * 16 * QPH << 1));
#pragma unroll
            for (int ng = 0; ng < 4; ng++) {
                mma16h(s[2*ng  ], aq[kk][0], aq[kk][1], aq[kk][2], aq[kk][3],
                       bk[ng][0], bk[ng][1]);
                mma16h(s[2*ng+1], aq[kk][0], aq[kk][1], aq[kk][2], aq[kk][3],
                       bk[ng][2], bk[ng][3]);
            }
        }

        // ---- causal mask (diagonal-region blocks only) ----
        if (j >= 2 * qb) {
            const int qr0 = qb * 128 + w * 16 + g;
            const int qr1 = qr0 + 8;
            const int jc  = j * 64;
#pragma unroll
            for (int nt = 0; nt < 8; nt++) {
                int c0 = jc + nt * 8 + tir * 2;
                int c1 = c0 + 1;
                if (c0 > qr0) s[nt][0] = -1e30f;
                if (c1 > qr0) s[nt][1] = -1e30f;
                if (c0 > qr1) s[nt][2] = -1e30f;
                if (c1 > qr1) s[nt][3] = -1e30f;
            }
        }

        // ---- online softmax (exp2 domain) ----
        float rm0 = -1e30f, rm1 = -1e30f;
#pragma unroll
        for (int nt = 0; nt < 8; nt++) {
            rm0 = fmaxf(rm0, fmaxf(s[nt][0], s[nt][1]));
            rm1 = fmaxf(rm1, fmaxf(s[nt][2], s[nt][3]));
        }
        rm0 = fmaxf(rm0, __shfl_xor_sync(0xffffffffu, rm0, 1));
        rm0 = fmaxf(rm0, __shfl_xor_sync(0xffffffffu, rm0, 2));
        rm1 = fmaxf(rm1, __shfl_xor_sync(0xffffffffu, rm1, 1));
        rm1 = fmaxf(rm1, __shfl_xor_sync(0xffffffffu, rm1, 2));

        float nm0 = fmaxf(m0, rm0), nm1 = fmaxf(m1, rm1);
        float cf0 = exp2f(m0 - nm0), cf1 = exp2f(m1 - nm1);
        m0 = nm0; m1 = nm1;

        // P via ex2.approx.f16x2 (d computed fp32, rounded fp16)
        uint32_t phA[8], phB[8];
#pragma unroll
        for (int nt = 0; nt < 8; nt++) {
            phA[nt] = ex2h2(h2(s[nt][0] - nm0, s[nt][1] - nm0));
            phB[nt] = ex2h2(h2(s[nt][2] - nm1, s[nt][3] - nm1));
        }

#pragma unroll
        for (int nt = 0; nt < 8; nt++) {
            o[nt][0] *= cf0; o[nt][1] *= cf0;
            o[nt][2] *= cf1; o[nt][3] *= cf1;
        }
        ol[0] *= cf0; ol[1] *= cf0; ol[2] *= cf1; ol[3] *= cf1;

        // ---- O += P @ V ; ol += P @ ones ----
#pragma unroll
        for (int kk = 0; kk < 4; kk++) {
            const uint32_t vk = vBase + vStg + (uint32_t)(kk * 16 * VSB);
#pragma unroll
            for (int ng = 0; ng < 4; ng++) {
                uint32_t bv[4];
                ldsm4t(bv[0], bv[1], bv[2], bv[3], vk + (uint32_t)(ng * 32));
                mma16h(o[2*ng  ], phA[2*kk], phB[2*kk],
                       phA[2*kk+1], phB[2*kk+1], bv[0], bv[1]);
                mma16h(o[2*ng+1], phA[2*kk], phB[2*kk],
                       phA[2*kk+1], phB[2*kk+1], bv[2], bv[3]);
            }
            mma16h(ol, phA[2*kk], phB[2*kk], phA[2*kk+1], phB[2*kk+1],
                   ONE2, ONE2);
        }
        __syncthreads();
    }

    // ---- normalize, write O fp16 [B,T,C] ----
    const float inv0 = 1.f / ol[0];
    const float inv1 = 1.f / ol[2];
    const int t0 = qb * 128 + w * 16 + g;
#pragma unroll
    for (int nt = 0; nt < 8; nt++) {
        int d = nt * 8 + tir * 2;
        *(__half2*)(O + (size_t)(b * TT + t0    ) * CC + h * DD + d) =
            __floats2half2_rn(o[nt][0] * inv0, o[nt][1] * inv0);
        *(__half2*)(O + (size_t)(b * TT + t0 + 8) * CC + h * DD + d) =
            __floats2half2_rn(o[nt][2] * inv1, o[nt][3] * inv1);
    }
    __syncthreads();   // smem quiescent before next tile restages
}

__global__ void __launch_bounds__(256, 2)
flash_kernel()
{
    extern __shared__ char fsm[];

    const __half* qkvh = (const __half*)g_qkv;
    __half* O = (__half*)g_att;

    const int bh  = blockIdx.y;
    const int b   = bh >> 4;
    const int h   = bh & 15;
    const int tid = threadIdx.x;
    const int w   = tid >> 5;
    const int lane = tid & 31;
    const int g   = lane >> 2;
    const int tir = lane & 3;

    const int aRow = (lane & 7) + ((lane >> 3) & 1) * 8;
    const int aColH = (lane >> 4) * 8;
    const int bRow = (lane & 7) + (lane >> 4) * 8;
    const int bColH = ((lane >> 3) & 1) * 8;

    const uint32_t smb   = smem_u32(fsm);
    const uint32_t qBase = smb + QS_OFF + (((w * 16 + aRow) * QPH + aColH) << 1);
    const uint32_t kBase = smb + KS_OFF + ((bRow * QPH + bColH) << 1);
    const uint32_t vBase = smb + VS_OFF
                         + ((lane & 7) + 8 * ((lane >> 3) & 1)) * VSB
                         + (lane >> 4) * 16;

    const __half* qrow = qkvh + (size_t)(b * TT) * 3 * CC + h * DD;
    const __half* krow = qrow + CC;
    const __half* vrow = qrow + 2 * CC;

    // Balanced causal pair: qb = p (light) then NQB-1-p (heavy); total work
    // per CTA = (2p+2) + (2(NQB-1-p)+2) = 2*NQB + 2 = 34 block-iters, uniform.
    flash_tile(fsm, qrow, krow, vrow, O, b, h, (int)blockIdx.x,
               tid, w, lane, g, tir, qBase, kBase, vBase);
    flash_tile(fsm, qrow, krow, vrow, O, b, h, NQB - 1 - (int)blockIdx.x,
               tid, w, lane, g, tir, qBase, kBase, vBase);
}

// ---------------------------------------------------------------------------
// Launch
// ---------------------------------------------------------------------------
extern "C" void kernel_launch(void* const* d_in, const int* in_sizes, int n_in,
                              void* d_out, int out_size)
{
    const float* x      = (const float*)d_in[0];
    const float* w_qkv  = (const float*)d_in[1];
    const float* w_proj = (const float*)d_in[2];
    const float* b_proj = (const float*)d_in[3];
    float* out = (float*)d_out;

    cudaFuncSetAttribute(gemm_qkv_kernel,
                         cudaFuncAttributeMaxDynamicSharedMemorySize, GEMM_SMEM);
    cudaFuncSetAttribute(gemm_proj_kernel,
                         cudaFuncAttributeMaxDynamicSharedMemorySize, GEMM_SMEM);
    cudaFuncSetAttribute(flash_kernel,
                         cudaFuncAttributeMaxDynamicSharedMemorySize, FLASH_SMEM);

    // 0) x -> fp16; w_qkv -> w_qkv^T fp16 in g_att
    cvt_x_kernel<<<(MTOT * CC / 4) / 256, 256>>>(x);
    transpose_wqkv_kernel<<<dim3(3 * CC / 32, CC / 32), dim3(32, 8)>>>(w_qkv);

    // 1) QKV projection (fp16, BK=64): Q scaled by 0.125*log2e
    gemm_qkv_kernel<<<dim3(3 * CC / 128, MTOT / 128), 256, GEMM_SMEM>>>();

    // 2) Fused causal flash attention (balanced pairs): -> g_att fp16
    flash_kernel<<<dim3(NQB / 2, BB * HH), 256, FLASH_SMEM>>>();

    // 3) w_proj -> w_proj^T fp16 (x region, dead after QKV GEMM)
    transpose_wproj_kernel<<<dim3(CC / 32, CC / 32), dim3(32, 8)>>>(w_proj);

    // 4) Output projection + bias (fp16 GEMM, fp32 out)
    gemm_proj_kernel<<<dim3(CC / 128, MTOT / 128), 256, GEMM_SMEM>>>(b_proj, out);
}